// round 1
// baseline (speedup 1.0000x reference)
#include <cuda_runtime.h>
#include <math.h>

#define TOK 131072   // B * H * W = B_ * N
#define CCH 256
#define HID 1024

// ---------------- scratch (device globals: no allocation allowed) -------------
static __device__ float g_rw[(size_t)TOK * CCH];      // LN1(ref) windowed
static __device__ float g_aw[(size_t)TOK * CCH];      // LN1(adj) windowed
static __device__ float g_q [(size_t)TOK * CCH];      // q  (token-major, col = head*32+d)
static __device__ float g_kv[(size_t)TOK * 2 * CCH];  // k | v
static __device__ float g_ao[(size_t)TOK * CCH];      // attention out (window order)
static __device__ float g_x [(size_t)TOK * CCH];      // residual-1 result (original order)
static __device__ float g_l2[(size_t)TOK * CCH];      // LN2 out
static __device__ float g_h [(size_t)TOK * HID];      // fc1/gelu out

// ---------------- helpers ----------------------------------------------------
__device__ __forceinline__ float4 warp_red4(float4 v) {
    #pragma unroll
    for (int o = 16; o > 0; o >>= 1) {
        v.x += __shfl_down_sync(0xffffffffu, v.x, o);
        v.y += __shfl_down_sync(0xffffffffu, v.y, o);
        v.z += __shfl_down_sync(0xffffffffu, v.z, o);
        v.w += __shfl_down_sync(0xffffffffu, v.w, o);
    }
    return v;
}

// token t (window order) -> source/dest row in (B, H*W) layout, with +4 shift
__device__ __forceinline__ int shifted_row(int t) {
    int b_ = t >> 6, n = t & 63;
    int bi = b_ >> 8, wi = b_ & 255;
    int h = ((((wi >> 4) << 3) | (n >> 3)) + 4) & 127;
    int w = ((((wi & 15) << 3) | (n & 7)) + 4) & 127;
    return (bi << 14) | (h << 7) | w;
}

// ---------------- LN1 + shift + window partition ------------------------------
__global__ void ln1_kernel(const float* __restrict__ ref, const float* __restrict__ adj,
                           const float* __restrict__ g, const float* __restrict__ b) {
    int t = blockIdx.x, c = threadIdx.x;
    int src = shifted_row(t) * 256 + c;
    float xr = ref[src], xa = adj[src];

    float4 v = warp_red4(make_float4(xr, xr * xr, xa, xa * xa));
    __shared__ float4 red[8];
    __shared__ float4 st;
    int lane = c & 31, wp = c >> 5;
    if (!lane) red[wp] = v;
    __syncthreads();
    if (c == 0) {
        float4 a = red[0];
        #pragma unroll
        for (int i = 1; i < 8; i++) { a.x += red[i].x; a.y += red[i].y; a.z += red[i].z; a.w += red[i].w; }
        float mr = a.x * (1.f / 256.f), ma = a.z * (1.f / 256.f);
        float vr = a.y * (1.f / 256.f) - mr * mr;
        float va = a.w * (1.f / 256.f) - ma * ma;
        st = make_float4(mr, rsqrtf(vr + 1e-5f), ma, rsqrtf(va + 1e-5f));
    }
    __syncthreads();
    float4 s = st;
    int o = t * 256 + c;
    float gc = g[c], bc = b[c];
    g_rw[o] = (xr - s.x) * s.y * gc + bc;
    g_aw[o] = (xa - s.z) * s.w * gc + bc;
}

// ---------------- LN2 ---------------------------------------------------------
__global__ void ln2_kernel(const float* __restrict__ g, const float* __restrict__ b) {
    int t = blockIdx.x, c = threadIdx.x;
    float x = g_x[t * 256 + c];
    float4 v = warp_red4(make_float4(x, x * x, 0.f, 0.f));
    __shared__ float4 red[8];
    __shared__ float2 st;
    int lane = c & 31, wp = c >> 5;
    if (!lane) red[wp] = v;
    __syncthreads();
    if (c == 0) {
        float sx = 0.f, sxx = 0.f;
        #pragma unroll
        for (int i = 0; i < 8; i++) { sx += red[i].x; sxx += red[i].y; }
        float m = sx * (1.f / 256.f);
        float var = sxx * (1.f / 256.f) - m * m;
        st = make_float2(m, rsqrtf(var + 1e-5f));
    }
    __syncthreads();
    float2 s = st;
    g_l2[t * 256 + c] = (x - s.x) * s.y * g[c] + b[c];
}

// ---------------- SGEMM 128x128x16, 8x8 micro-tiles ---------------------------
// MODE 0: C = A*W + bias
// MODE 1: proj epilogue: scatter (window-reverse + unshift) + shortcut residual
// MODE 2: gelu(A*W + bias)
// MODE 3: C = A*W + bias + extra  (final output)
template <int MODE>
__global__ void __launch_bounds__(256)
sgemm(const float* __restrict__ A, const float* __restrict__ W,
      const float* __restrict__ bias, float* __restrict__ C,
      int M, int N, int K, const float* __restrict__ extra) {
    __shared__ float As[16][132];
    __shared__ float Bs[16][132];

    int tid = threadIdx.x;
    int bm = blockIdx.y << 7;
    int bn = blockIdx.x << 7;
    int ty = tid >> 4, tx = tid & 15;

    float acc[8][8];
    #pragma unroll
    for (int i = 0; i < 8; i++)
        #pragma unroll
        for (int j = 0; j < 8; j++) acc[i][j] = 0.f;

    int ar = tid >> 2;
    int ac = (tid & 3) << 2;
    int br = tid >> 5;
    int bc = (tid & 31) << 2;
    const float* Aptr = A + (size_t)(bm + ar) * K + ac;
    const float* Wptr = W + (size_t)br * N + bn + bc;

    for (int k0 = 0; k0 < K; k0 += 16) {
        float4 a0 = *(const float4*)(Aptr + k0);
        float4 a1 = *(const float4*)(Aptr + (size_t)64 * K + k0);
        float4 b0 = *(const float4*)(Wptr + (size_t)k0 * N);
        float4 b1 = *(const float4*)(Wptr + (size_t)(k0 + 8) * N);
        if (k0) __syncthreads();
        As[ac + 0][ar] = a0.x; As[ac + 1][ar] = a0.y; As[ac + 2][ar] = a0.z; As[ac + 3][ar] = a0.w;
        As[ac + 0][ar + 64] = a1.x; As[ac + 1][ar + 64] = a1.y; As[ac + 2][ar + 64] = a1.z; As[ac + 3][ar + 64] = a1.w;
        *(float4*)&Bs[br][bc] = b0;
        *(float4*)&Bs[br + 8][bc] = b1;
        __syncthreads();
        #pragma unroll
        for (int kk = 0; kk < 16; kk++) {
            float4 af0 = *(const float4*)&As[kk][ty << 3];
            float4 af1 = *(const float4*)&As[kk][(ty << 3) + 4];
            float4 bf0 = *(const float4*)&Bs[kk][tx << 3];
            float4 bf1 = *(const float4*)&Bs[kk][(tx << 3) + 4];
            float a[8] = {af0.x, af0.y, af0.z, af0.w, af1.x, af1.y, af1.z, af1.w};
            float bb[8] = {bf0.x, bf0.y, bf0.z, bf0.w, bf1.x, bf1.y, bf1.z, bf1.w};
            #pragma unroll
            for (int i = 0; i < 8; i++)
                #pragma unroll
                for (int j = 0; j < 8; j++) acc[i][j] += a[i] * bb[j];
        }
    }

    int cb = bn + (tx << 3);
    float4 bv0 = *(const float4*)&bias[cb];
    float4 bv1 = *(const float4*)&bias[cb + 4];
    float bv[8] = {bv0.x, bv0.y, bv0.z, bv0.w, bv1.x, bv1.y, bv1.z, bv1.w};

    #pragma unroll
    for (int i = 0; i < 8; i++) {
        int m = bm + (ty << 3) + i;
        float o[8];
        #pragma unroll
        for (int j = 0; j < 8; j++) o[j] = acc[i][j] + bv[j];

        if (MODE == 2) {
            #pragma unroll
            for (int j = 0; j < 8; j++)
                o[j] = 0.5f * o[j] * (1.0f + erff(o[j] * 0.70710678118654752f));
        }
        if (MODE == 1) {
            int dst = shifted_row(m);
            const float4* sc = (const float4*)&extra[(size_t)dst * 256 + cb];
            float4 s0 = sc[0], s1 = sc[1];
            o[0] += s0.x; o[1] += s0.y; o[2] += s0.z; o[3] += s0.w;
            o[4] += s1.x; o[5] += s1.y; o[6] += s1.z; o[7] += s1.w;
            float4* dp = (float4*)&C[(size_t)dst * 256 + cb];
            dp[0] = make_float4(o[0], o[1], o[2], o[3]);
            dp[1] = make_float4(o[4], o[5], o[6], o[7]);
        } else if (MODE == 3) {
            const float4* xr = (const float4*)&extra[(size_t)m * 256 + cb];
            float4 x0 = xr[0], x1 = xr[1];
            o[0] += x0.x; o[1] += x0.y; o[2] += x0.z; o[3] += x0.w;
            o[4] += x1.x; o[5] += x1.y; o[6] += x1.z; o[7] += x1.w;
            float4* dp = (float4*)&C[(size_t)m * N + cb];
            dp[0] = make_float4(o[0], o[1], o[2], o[3]);
            dp[1] = make_float4(o[4], o[5], o[6], o[7]);
        } else {
            float4* dp = (float4*)&C[(size_t)m * N + cb];
            dp[0] = make_float4(o[0], o[1], o[2], o[3]);
            dp[1] = make_float4(o[4], o[5], o[6], o[7]);
        }
    }
}

// ---------------- windowed attention ------------------------------------------
// one block per (window, head); 64 threads, thread n owns full query row n
__global__ void __launch_bounds__(64)
attn_kernel(const float* __restrict__ q, const float* __restrict__ kv,
            const float* __restrict__ rel, const float* __restrict__ mask,
            float* __restrict__ out) {
    __shared__ float ks[64][36];
    __shared__ float vs[64][36];
    int blk = blockIdx.x;
    int b_ = blk >> 3, head = blk & 7;
    int tid = threadIdx.x;
    int t0 = b_ << 6;

    const float* kvrow = kv + (size_t)(t0 + tid) * 512 + (head << 5);
    #pragma unroll
    for (int d4 = 0; d4 < 8; d4++) {
        *(float4*)&ks[tid][d4 * 4] = *(const float4*)(kvrow + d4 * 4);
        *(float4*)&vs[tid][d4 * 4] = *(const float4*)(kvrow + 256 + d4 * 4);
    }
    float qr[32];
    const float* qrow = q + (size_t)(t0 + tid) * 256 + (head << 5);
    #pragma unroll
    for (int d4 = 0; d4 < 8; d4++) {
        float4 f = *(const float4*)(qrow + d4 * 4);
        qr[d4 * 4 + 0] = f.x; qr[d4 * 4 + 1] = f.y; qr[d4 * 4 + 2] = f.z; qr[d4 * 4 + 3] = f.w;
    }
    __syncthreads();

    const int n = tid;
    int i1 = n >> 3, j1 = n & 7;
    const float* mrow = mask + ((b_ & 255) << 12) + (n << 6);
    const float scale = 0.17677669529663687f;  // 1/sqrt(32)

    float s[64];
    float mx = -1e30f;
    #pragma unroll
    for (int m = 0; m < 64; m++) {
        float dot = 0.f;
        #pragma unroll
        for (int d4 = 0; d4 < 8; d4++) {
            float4 kf = *(const float4*)&ks[m][d4 * 4];
            dot += qr[d4 * 4 + 0] * kf.x + qr[d4 * 4 + 1] * kf.y
                 + qr[d4 * 4 + 2] * kf.z + qr[d4 * 4 + 3] * kf.w;
        }
        int i2 = m >> 3, j2 = m & 7;
        int idx = (i1 - i2 + 7) * 15 + (j1 - j2 + 7);
        float val = dot * scale + rel[idx * 8 + head] + mrow[m];
        s[m] = val;
        mx = fmaxf(mx, val);
    }
    float sum = 0.f;
    #pragma unroll
    for (int m = 0; m < 64; m++) { s[m] = expf(s[m] - mx); sum += s[m]; }
    float inv = 1.f / sum;

    float accv[32];
    #pragma unroll
    for (int d = 0; d < 32; d++) accv[d] = 0.f;
    #pragma unroll
    for (int m = 0; m < 64; m++) {
        float pm = s[m] * inv;
        #pragma unroll
        for (int d4 = 0; d4 < 8; d4++) {
            float4 vf = *(const float4*)&vs[m][d4 * 4];
            accv[d4 * 4 + 0] += pm * vf.x; accv[d4 * 4 + 1] += pm * vf.y;
            accv[d4 * 4 + 2] += pm * vf.z; accv[d4 * 4 + 3] += pm * vf.w;
        }
    }
    float* orow = out + (size_t)(t0 + n) * 256 + (head << 5);
    #pragma unroll
    for (int d4 = 0; d4 < 8; d4++)
        *(float4*)(orow + d4 * 4) = make_float4(accv[d4 * 4 + 0], accv[d4 * 4 + 1],
                                                accv[d4 * 4 + 2], accv[d4 * 4 + 3]);
}

// ---------------- launch -------------------------------------------------------
extern "C" void kernel_launch(void* const* d_in, const int* in_sizes, int n_in,
                              void* d_out, int out_size) {
    (void)in_sizes; (void)n_in; (void)out_size;
    const float* ref  = (const float*)d_in[0];
    const float* adj  = (const float*)d_in[1];
    const float* mask = (const float*)d_in[2];
    // d_in[3]=H, d_in[4]=W (constants: 128)
    const float* n1g = (const float*)d_in[5];
    const float* n1b = (const float*)d_in[6];
    const float* qw  = (const float*)d_in[7];
    const float* qb  = (const float*)d_in[8];
    const float* kvw = (const float*)d_in[9];
    const float* kvb = (const float*)d_in[10];
    const float* rel = (const float*)d_in[11];
    const float* pw  = (const float*)d_in[12];
    const float* pb  = (const float*)d_in[13];
    const float* n2g = (const float*)d_in[14];
    const float* n2b = (const float*)d_in[15];
    const float* f1w = (const float*)d_in[16];
    const float* f1b = (const float*)d_in[17];
    const float* f2w = (const float*)d_in[18];
    const float* f2b = (const float*)d_in[19];
    float* out = (float*)d_out;

    float *rw, *aw, *q, *kv, *ao, *x, *l2, *h;
    cudaGetSymbolAddress((void**)&rw, g_rw);
    cudaGetSymbolAddress((void**)&aw, g_aw);
    cudaGetSymbolAddress((void**)&q,  g_q);
    cudaGetSymbolAddress((void**)&kv, g_kv);
    cudaGetSymbolAddress((void**)&ao, g_ao);
    cudaGetSymbolAddress((void**)&x,  g_x);
    cudaGetSymbolAddress((void**)&l2, g_l2);
    cudaGetSymbolAddress((void**)&h,  g_h);

    // 1. LN1 + shift + window partition
    ln1_kernel<<<TOK, 256>>>(ref, adj, n1g, n1b);
    // 2. q = rw @ q_w + q_b
    sgemm<0><<<dim3(2, 1024), 256>>>(rw, qw, qb, q, TOK, 256, 256, nullptr);
    // 3. kv = aw @ kv_w + kv_b
    sgemm<0><<<dim3(4, 1024), 256>>>(aw, kvw, kvb, kv, TOK, 512, 256, nullptr);
    // 4. windowed attention
    attn_kernel<<<16384, 64>>>(q, kv, rel, mask, ao);
    // 5. proj + window-reverse + unshift + residual -> x
    sgemm<1><<<dim3(2, 1024), 256>>>(ao, pw, pb, x, TOK, 256, 256, ref);
    // 6. LN2
    ln2_kernel<<<TOK, 256>>>(n2g, n2b);
    // 7. fc1 + GELU
    sgemm<2><<<dim3(8, 1024), 256>>>(l2, f1w, f1b, h, TOK, 1024, 256, nullptr);
    // 8. fc2 + residual -> out
    sgemm<3><<<dim3(2, 1024), 256>>>(h, f2w, f2b, out, TOK, 256, 1024, x);
}

// round 2
// speedup vs baseline: 1.6151x; 1.6151x over previous
#include <cuda_runtime.h>
#include <math.h>

#define TOK 131072   // B * H * W = B_ * N
#define CCH 256
#define HID 1024

// ---------------- scratch (device globals: no allocation allowed) -------------
static __device__ float g_rw[(size_t)TOK * CCH];      // LN1(ref) windowed
static __device__ float g_aw[(size_t)TOK * CCH];      // LN1(adj) windowed
static __device__ float g_q [(size_t)TOK * CCH];      // q  (token-major, col = head*32+d)
static __device__ float g_kv[(size_t)TOK * 2 * CCH];  // k | v
static __device__ float g_ao[(size_t)TOK * CCH];      // attention out (window order)
static __device__ float g_x [(size_t)TOK * CCH];      // residual-1 result (original order)
static __device__ float g_l2[(size_t)TOK * CCH];      // LN2 out
static __device__ float g_h [(size_t)TOK * HID];      // fc1/gelu out

// ---------------- helpers ----------------------------------------------------
__device__ __forceinline__ float4 warp_red4(float4 v) {
    #pragma unroll
    for (int o = 16; o > 0; o >>= 1) {
        v.x += __shfl_down_sync(0xffffffffu, v.x, o);
        v.y += __shfl_down_sync(0xffffffffu, v.y, o);
        v.z += __shfl_down_sync(0xffffffffu, v.z, o);
        v.w += __shfl_down_sync(0xffffffffu, v.w, o);
    }
    return v;
}

// token t (window order) -> source/dest row in (B, H*W) layout, with +4 shift
__device__ __forceinline__ int shifted_row(int t) {
    int b_ = t >> 6, n = t & 63;
    int bi = b_ >> 8, wi = b_ & 255;
    int h = ((((wi >> 4) << 3) | (n >> 3)) + 4) & 127;
    int w = ((((wi & 15) << 3) | (n & 7)) + 4) & 127;
    return (bi << 14) | (h << 7) | w;
}

// ---------------- LN1 + shift + window partition ------------------------------
__global__ void ln1_kernel(const float* __restrict__ ref, const float* __restrict__ adj,
                           const float* __restrict__ g, const float* __restrict__ b) {
    int t = blockIdx.x, c = threadIdx.x;
    int src = shifted_row(t) * 256 + c;
    float xr = ref[src], xa = adj[src];

    float4 v = warp_red4(make_float4(xr, xr * xr, xa, xa * xa));
    __shared__ float4 red[8];
    __shared__ float4 st;
    int lane = c & 31, wp = c >> 5;
    if (!lane) red[wp] = v;
    __syncthreads();
    if (c == 0) {
        float4 a = red[0];
        #pragma unroll
        for (int i = 1; i < 8; i++) { a.x += red[i].x; a.y += red[i].y; a.z += red[i].z; a.w += red[i].w; }
        float mr = a.x * (1.f / 256.f), ma = a.z * (1.f / 256.f);
        float vr = a.y * (1.f / 256.f) - mr * mr;
        float va = a.w * (1.f / 256.f) - ma * ma;
        st = make_float4(mr, rsqrtf(vr + 1e-5f), ma, rsqrtf(va + 1e-5f));
    }
    __syncthreads();
    float4 s = st;
    int o = t * 256 + c;
    float gc = g[c], bc = b[c];
    g_rw[o] = (xr - s.x) * s.y * gc + bc;
    g_aw[o] = (xa - s.z) * s.w * gc + bc;
}

// ---------------- LN2 ---------------------------------------------------------
__global__ void ln2_kernel(const float* __restrict__ g, const float* __restrict__ b) {
    int t = blockIdx.x, c = threadIdx.x;
    float x = g_x[t * 256 + c];
    float4 v = warp_red4(make_float4(x, x * x, 0.f, 0.f));
    __shared__ float4 red[8];
    __shared__ float2 st;
    int lane = c & 31, wp = c >> 5;
    if (!lane) red[wp] = v;
    __syncthreads();
    if (c == 0) {
        float sx = 0.f, sxx = 0.f;
        #pragma unroll
        for (int i = 0; i < 8; i++) { sx += red[i].x; sxx += red[i].y; }
        float m = sx * (1.f / 256.f);
        float var = sxx * (1.f / 256.f) - m * m;
        st = make_float2(m, rsqrtf(var + 1e-5f));
    }
    __syncthreads();
    float2 s = st;
    g_l2[t * 256 + c] = (x - s.x) * s.y * g[c] + b[c];
}

// ---------------- SGEMM 128x128x16, 8x8 micro-tiles ---------------------------
// MODE 0: C = A*W + bias
// MODE 1: proj epilogue: scatter (window-reverse + unshift) + shortcut residual
// MODE 2: gelu(A*W + bias)
// MODE 3: C = A*W + bias + extra  (final output)
template <int MODE>
__global__ void __launch_bounds__(256)
sgemm(const float* __restrict__ A, const float* __restrict__ W,
      const float* __restrict__ bias, float* __restrict__ C,
      int M, int N, int K, const float* __restrict__ extra) {
    __shared__ float As[16][132];
    __shared__ float Bs[16][132];

    int tid = threadIdx.x;
    int bm = blockIdx.y << 7;
    int bn = blockIdx.x << 7;
    int ty = tid >> 4, tx = tid & 15;

    float acc[8][8];
    #pragma unroll
    for (int i = 0; i < 8; i++)
        #pragma unroll
        for (int j = 0; j < 8; j++) acc[i][j] = 0.f;

    int ar = tid >> 2;
    int ac = (tid & 3) << 2;
    int br = tid >> 5;
    int bc = (tid & 31) << 2;
    const float* Aptr = A + (size_t)(bm + ar) * K + ac;
    const float* Wptr = W + (size_t)br * N + bn + bc;

    for (int k0 = 0; k0 < K; k0 += 16) {
        float4 a0 = *(const float4*)(Aptr + k0);
        float4 a1 = *(const float4*)(Aptr + (size_t)64 * K + k0);
        float4 b0 = *(const float4*)(Wptr + (size_t)k0 * N);
        float4 b1 = *(const float4*)(Wptr + (size_t)(k0 + 8) * N);
        if (k0) __syncthreads();
        As[ac + 0][ar] = a0.x; As[ac + 1][ar] = a0.y; As[ac + 2][ar] = a0.z; As[ac + 3][ar] = a0.w;
        As[ac + 0][ar + 64] = a1.x; As[ac + 1][ar + 64] = a1.y; As[ac + 2][ar + 64] = a1.z; As[ac + 3][ar + 64] = a1.w;
        *(float4*)&Bs[br][bc] = b0;
        *(float4*)&Bs[br + 8][bc] = b1;
        __syncthreads();
        #pragma unroll
        for (int kk = 0; kk < 16; kk++) {
            float4 af0 = *(const float4*)&As[kk][ty << 3];
            float4 af1 = *(const float4*)&As[kk][(ty << 3) + 4];
            float4 bf0 = *(const float4*)&Bs[kk][tx << 3];
            float4 bf1 = *(const float4*)&Bs[kk][(tx << 3) + 4];
            float a[8] = {af0.x, af0.y, af0.z, af0.w, af1.x, af1.y, af1.z, af1.w};
            float bb[8] = {bf0.x, bf0.y, bf0.z, bf0.w, bf1.x, bf1.y, bf1.z, bf1.w};
            #pragma unroll
            for (int i = 0; i < 8; i++)
                #pragma unroll
                for (int j = 0; j < 8; j++) acc[i][j] += a[i] * bb[j];
        }
    }

    int cb = bn + (tx << 3);
    float4 bv0 = *(const float4*)&bias[cb];
    float4 bv1 = *(const float4*)&bias[cb + 4];
    float bv[8] = {bv0.x, bv0.y, bv0.z, bv0.w, bv1.x, bv1.y, bv1.z, bv1.w};

    #pragma unroll
    for (int i = 0; i < 8; i++) {
        int m = bm + (ty << 3) + i;
        float o[8];
        #pragma unroll
        for (int j = 0; j < 8; j++) o[j] = acc[i][j] + bv[j];

        if (MODE == 2) {
            #pragma unroll
            for (int j = 0; j < 8; j++)
                o[j] = 0.5f * o[j] * (1.0f + erff(o[j] * 0.70710678118654752f));
        }
        if (MODE == 1) {
            int dst = shifted_row(m);
            const float4* sc = (const float4*)&extra[(size_t)dst * 256 + cb];
            float4 s0 = sc[0], s1 = sc[1];
            o[0] += s0.x; o[1] += s0.y; o[2] += s0.z; o[3] += s0.w;
            o[4] += s1.x; o[5] += s1.y; o[6] += s1.z; o[7] += s1.w;
            float4* dp = (float4*)&C[(size_t)dst * 256 + cb];
            dp[0] = make_float4(o[0], o[1], o[2], o[3]);
            dp[1] = make_float4(o[4], o[5], o[6], o[7]);
        } else if (MODE == 3) {
            const float4* xr = (const float4*)&extra[(size_t)m * 256 + cb];
            float4 x0 = xr[0], x1 = xr[1];
            o[0] += x0.x; o[1] += x0.y; o[2] += x0.z; o[3] += x0.w;
            o[4] += x1.x; o[5] += x1.y; o[6] += x1.z; o[7] += x1.w;
            float4* dp = (float4*)&C[(size_t)m * N + cb];
            dp[0] = make_float4(o[0], o[1], o[2], o[3]);
            dp[1] = make_float4(o[4], o[5], o[6], o[7]);
        } else {
            float4* dp = (float4*)&C[(size_t)m * N + cb];
            dp[0] = make_float4(o[0], o[1], o[2], o[3]);
            dp[1] = make_float4(o[4], o[5], o[6], o[7]);
        }
    }
}

// ---------------- windowed attention ------------------------------------------
// one block per (window, head); 64 threads, thread n owns full query row n
__global__ void __launch_bounds__(64)
attn_kernel(const float* __restrict__ q, const float* __restrict__ kv,
            const float* __restrict__ rel, const float* __restrict__ mask,
            float* __restrict__ out) {
    __shared__ float ks[64][36];
    __shared__ float vs[64][36];
    int blk = blockIdx.x;
    int b_ = blk >> 3, head = blk & 7;
    int tid = threadIdx.x;
    int t0 = b_ << 6;

    const float* kvrow = kv + (size_t)(t0 + tid) * 512 + (head << 5);
    #pragma unroll
    for (int d4 = 0; d4 < 8; d4++) {
        *(float4*)&ks[tid][d4 * 4] = *(const float4*)(kvrow + d4 * 4);
        *(float4*)&vs[tid][d4 * 4] = *(const float4*)(kvrow + 256 + d4 * 4);
    }
    float qr[32];
    const float* qrow = q + (size_t)(t0 + tid) * 256 + (head << 5);
    #pragma unroll
    for (int d4 = 0; d4 < 8; d4++) {
        float4 f = *(const float4*)(qrow + d4 * 4);
        qr[d4 * 4 + 0] = f.x; qr[d4 * 4 + 1] = f.y; qr[d4 * 4 + 2] = f.z; qr[d4 * 4 + 3] = f.w;
    }
    __syncthreads();

    const int n = tid;
    int i1 = n >> 3, j1 = n & 7;
    const float* mrow = mask + ((b_ & 255) << 12) + (n << 6);
    const float scale = 0.17677669529663687f;  // 1/sqrt(32)

    float s[64];
    float mx = -1e30f;
    #pragma unroll
    for (int m = 0; m < 64; m++) {
        float dot = 0.f;
        #pragma unroll
        for (int d4 = 0; d4 < 8; d4++) {
            float4 kf = *(const float4*)&ks[m][d4 * 4];
            dot += qr[d4 * 4 + 0] * kf.x + qr[d4 * 4 + 1] * kf.y
                 + qr[d4 * 4 + 2] * kf.z + qr[d4 * 4 + 3] * kf.w;
        }
        int i2 = m >> 3, j2 = m & 7;
        int idx = (i1 - i2 + 7) * 15 + (j1 - j2 + 7);
        float val = dot * scale + rel[idx * 8 + head] + mrow[m];
        s[m] = val;
        mx = fmaxf(mx, val);
    }
    float sum = 0.f;
    #pragma unroll
    for (int m = 0; m < 64; m++) { s[m] = expf(s[m] - mx); sum += s[m]; }
    float inv = 1.f / sum;

    float accv[32];
    #pragma unroll
    for (int d = 0; d < 32; d++) accv[d] = 0.f;
    #pragma unroll
    for (int m = 0; m < 64; m++) {
        float pm = s[m] * inv;
        #pragma unroll
        for (int d4 = 0; d4 < 8; d4++) {
            float4 vf = *(const float4*)&vs[m][d4 * 4];
            accv[d4 * 4 + 0] += pm * vf.x; accv[d4 * 4 + 1] += pm * vf.y;
            accv[d4 * 4 + 2] += pm * vf.z; accv[d4 * 4 + 3] += pm * vf.w;
        }
    }
    float* orow = out + (size_t)(t0 + n) * 256 + (head << 5);
    #pragma unroll
    for (int d4 = 0; d4 < 8; d4++)
        *(float4*)(orow + d4 * 4) = make_float4(accv[d4 * 4 + 0], accv[d4 * 4 + 1],
                                                accv[d4 * 4 + 2], accv[d4 * 4 + 3]);
}

// ---------------- launch -------------------------------------------------------
extern "C" void kernel_launch(void* const* d_in, const int* in_sizes, int n_in,
                              void* d_out, int out_size) {
    (void)in_sizes; (void)n_in; (void)out_size;
    const float* ref  = (const float*)d_in[0];
    const float* adj  = (const float*)d_in[1];
    const float* mask = (const float*)d_in[2];
    // d_in[3]=H, d_in[4]=W (constants: 128)
    const float* n1g = (const float*)d_in[5];
    const float* n1b = (const float*)d_in[6];
    const float* qw  = (const float*)d_in[7];
    const float* qb  = (const float*)d_in[8];
    const float* kvw = (const float*)d_in[9];
    const float* kvb = (const float*)d_in[10];
    const float* rel = (const float*)d_in[11];
    const float* pw  = (const float*)d_in[12];
    const float* pb  = (const float*)d_in[13];
    const float* n2g = (const float*)d_in[14];
    const float* n2b = (const float*)d_in[15];
    const float* f1w = (const float*)d_in[16];
    const float* f1b = (const float*)d_in[17];
    const float* f2w = (const float*)d_in[18];
    const float* f2b = (const float*)d_in[19];
    float* out = (float*)d_out;

    float *rw, *aw, *q, *kv, *ao, *x, *l2, *h;
    cudaGetSymbolAddress((void**)&rw, g_rw);
    cudaGetSymbolAddress((void**)&aw, g_aw);
    cudaGetSymbolAddress((void**)&q,  g_q);
    cudaGetSymbolAddress((void**)&kv, g_kv);
    cudaGetSymbolAddress((void**)&ao, g_ao);
    cudaGetSymbolAddress((void**)&x,  g_x);
    cudaGetSymbolAddress((void**)&l2, g_l2);
    cudaGetSymbolAddress((void**)&h,  g_h);

    // 1. LN1 + shift + window partition
    ln1_kernel<<<TOK, 256>>>(ref, adj, n1g, n1b);
    // 2. q = rw @ q_w + q_b
    sgemm<0><<<dim3(2, 1024), 256>>>(rw, qw, qb, q, TOK, 256, 256, nullptr);
    // 3. kv = aw @ kv_w + kv_b
    sgemm<0><<<dim3(4, 1024), 256>>>(aw, kvw, kvb, kv, TOK, 512, 256, nullptr);
    // 4. windowed attention
    attn_kernel<<<16384, 64>>>(q, kv, rel, mask, ao);
    // 5. proj + window-reverse + unshift + residual -> x
    sgemm<1><<<dim3(2, 1024), 256>>>(ao, pw, pb, x, TOK, 256, 256, ref);
    // 6. LN2
    ln2_kernel<<<TOK, 256>>>(n2g, n2b);
    // 7. fc1 + GELU
    sgemm<2><<<dim3(8, 1024), 256>>>(l2, f1w, f1b, h, TOK, 1024, 256, nullptr);
    // 8. fc2 + residual -> out
    sgemm<3><<<dim3(2, 1024), 256>>>(h, f2w, f2b, out, TOK, 256, 1024, x);
}

// round 7
// speedup vs baseline: 3.5471x; 2.1962x over previous
#include <cuda_runtime.h>
#include <math.h>
#include <stdint.h>

#define TOK 131072
#define CCH 256
#define HID 1024

static __device__ float g_rw[(size_t)TOK * CCH];
static __device__ float g_aw[(size_t)TOK * CCH];
static __device__ float g_q [(size_t)TOK * CCH];
static __device__ float g_kv[(size_t)TOK * 2 * CCH];
static __device__ float g_ao[(size_t)TOK * CCH];
static __device__ float g_x [(size_t)TOK * CCH];
static __device__ float g_l2[(size_t)TOK * CCH];
static __device__ float g_h [(size_t)TOK * HID];
static __device__ float g_wt[786432];
#define WT_Q   0
#define WT_KV  65536
#define WT_P   196608
#define WT_F1  262144
#define WT_F2  524288

// ---------------- helpers ------------------------------------------------------
__device__ __forceinline__ uint32_t smem_u32(const void* p) {
    uint32_t a;
    asm("{ .reg .u64 t; cvta.to.shared.u64 t, %1; cvt.u32.u64 %0, t; }" : "=r"(a) : "l"(p));
    return a;
}
__device__ __forceinline__ float tf32r(float x) {
    uint32_t u;
    asm("cvt.rna.tf32.f32 %0, %1;" : "=r"(u) : "f"(x));
    return __uint_as_float(u);
}
__device__ __forceinline__ void cp16(uint32_t dst, const void* src) {
    asm volatile("cp.async.cg.shared.global [%0], [%1], 16;" :: "r"(dst), "l"(src));
}
__device__ __forceinline__ void cp_commit() { asm volatile("cp.async.commit_group;" ::: "memory"); }
__device__ __forceinline__ void cp_wait2()  { asm volatile("cp.async.wait_group 2;" ::: "memory"); }

#define LDSM4(r0, r1, r2, r3, addr) \
    asm volatile("ldmatrix.sync.aligned.m8n8.x4.shared.b16 {%0,%1,%2,%3}, [%4];" \
        : "=r"(r0), "=r"(r1), "=r"(r2), "=r"(r3) : "r"(addr))

#define MMA8(c, a, b0, b1) \
    asm volatile("mma.sync.aligned.m16n8k8.row.col.f32.tf32.tf32.f32 " \
        "{%0,%1,%2,%3}, {%4,%5,%6,%7}, {%8,%9}, {%0,%1,%2,%3};" \
        : "+f"((c)[0]), "+f"((c)[1]), "+f"((c)[2]), "+f"((c)[3]) \
        : "r"((a)[0]), "r"((a)[1]), "r"((a)[2]), "r"((a)[3]), "r"(b0), "r"(b1))

__device__ __forceinline__ int shifted_row(int t) {
    int b_ = t >> 6, n = t & 63;
    int bi = b_ >> 8, wi = b_ & 255;
    int h = ((((wi >> 4) << 3) | (n >> 3)) + 4) & 127;
    int w = ((((wi & 15) << 3) | (n & 7)) + 4) & 127;
    return (bi << 14) | (h << 7) | w;
}

// ---------------- weight transpose W[K][N] -> Wt[N][K], tf32-rounded -----------
__global__ void transpose_k(const float* __restrict__ W, float* __restrict__ Wt, int K, int N) {
    __shared__ float t[32][33];
    int n0 = blockIdx.x << 5, k0 = blockIdx.y << 5;
    int tx = threadIdx.x, ty = threadIdx.y;
    #pragma unroll
    for (int j = 0; j < 32; j += 8) t[ty + j][tx] = W[(size_t)(k0 + ty + j) * N + n0 + tx];
    __syncthreads();
    #pragma unroll
    for (int j = 0; j < 32; j += 8)
        Wt[(size_t)(n0 + ty + j) * K + k0 + tx] = tf32r(t[tx][ty + j]);
}

// ---------------- LayerNorms (outputs tf32-rounded: they feed mma A) -----------
__device__ __forceinline__ float4 warp_red4(float4 v) {
    #pragma unroll
    for (int o = 16; o > 0; o >>= 1) {
        v.x += __shfl_down_sync(~0u, v.x, o); v.y += __shfl_down_sync(~0u, v.y, o);
        v.z += __shfl_down_sync(~0u, v.z, o); v.w += __shfl_down_sync(~0u, v.w, o);
    }
    return v;
}
__global__ void ln1_kernel(const float* __restrict__ ref, const float* __restrict__ adj,
                           const float* __restrict__ g, const float* __restrict__ b) {
    int t = blockIdx.x, c = threadIdx.x;
    int src = shifted_row(t) * 256 + c;
    float xr = ref[src], xa = adj[src];
    float4 v = warp_red4(make_float4(xr, xr * xr, xa, xa * xa));
    __shared__ float4 red[8]; __shared__ float4 st;
    if (!(c & 31)) red[c >> 5] = v;
    __syncthreads();
    if (c == 0) {
        float4 a = red[0];
        #pragma unroll
        for (int i = 1; i < 8; i++) { a.x += red[i].x; a.y += red[i].y; a.z += red[i].z; a.w += red[i].w; }
        float mr = a.x * (1.f/256.f), ma = a.z * (1.f/256.f);
        st = make_float4(mr, rsqrtf(a.y*(1.f/256.f) - mr*mr + 1e-5f),
                         ma, rsqrtf(a.w*(1.f/256.f) - ma*ma + 1e-5f));
    }
    __syncthreads();
    float4 s = st; int o = t * 256 + c;
    float gc = g[c], bc = b[c];
    g_rw[o] = tf32r((xr - s.x) * s.y * gc + bc);
    g_aw[o] = tf32r((xa - s.z) * s.w * gc + bc);
}
__global__ void ln2_kernel(const float* __restrict__ g, const float* __restrict__ b) {
    int t = blockIdx.x, c = threadIdx.x;
    float x = g_x[t * 256 + c];
    float4 v = warp_red4(make_float4(x, x * x, 0.f, 0.f));
    __shared__ float4 red[8]; __shared__ float2 st;
    if (!(c & 31)) red[c >> 5] = v;
    __syncthreads();
    if (c == 0) {
        float sx = 0.f, sxx = 0.f;
        #pragma unroll
        for (int i = 0; i < 8; i++) { sx += red[i].x; sxx += red[i].y; }
        float m = sx * (1.f/256.f);
        st = make_float2(m, rsqrtf(sxx*(1.f/256.f) - m*m + 1e-5f));
    }
    __syncthreads();
    float2 s = st;
    g_l2[t * 256 + c] = tf32r((x - s.x) * s.y * g[c] + b[c]);
}

// ---------------- tf32 mma.sync GEMM: BM=128, BN=128, BK=32, 3-stage -----------
#define ST 3
#define STG_BYTES 32768
#define GEMM_SMEM (ST * STG_BYTES)   // 96 KB

__device__ __forceinline__ void gload(uint32_t sA, uint32_t sB,
        const float* Ab, const float* Bb, int K, int k0, int tid) {
    #pragma unroll
    for (int i = 0; i < 4; i++) {
        int id = (tid << 2) + i;
        int row = id >> 3, u = id & 7;
        uint32_t off = (uint32_t)(row << 7) + (((u ^ (row & 7))) << 4);
        cp16(sA + off, Ab + (size_t)row * K + k0 + (u << 2));
        cp16(sB + off, Bb + (size_t)row * K + k0 + (u << 2));
    }
}

// MODE 0: C=AB+bias  1: proj scatter+residual  2: gelu(+tf32 round)  3: +extra
template <int MODE>
__global__ void __launch_bounds__(256, 2)
gemm_mma(const float* __restrict__ A, const float* __restrict__ Bt,
         const float* __restrict__ bias, float* __restrict__ C,
         int K, int N, const float* __restrict__ extra) {
    extern __shared__ __align__(128) char smem[];
    uint32_t sbase = smem_u32(smem);
    int tid = threadIdx.x;
    int lane = tid & 31, wid = tid >> 5;
    int wm = wid & 3, wn = wid >> 2;
    size_t bm = (size_t)blockIdx.y << 7;
    int bn = blockIdx.x << 7;

    const float* Ab = A + bm * K;
    const float* Bb = Bt + (size_t)bn * K;
    int nch = K >> 5;

    float c[2][8][4];
    #pragma unroll
    for (int i = 0; i < 2; i++)
        #pragma unroll
        for (int j = 0; j < 8; j++)
            #pragma unroll
            for (int k = 0; k < 4; k++) c[i][j][k] = 0.f;

    for (int p = 0; p < ST; p++) {
        gload(sbase + p * STG_BYTES, sbase + p * STG_BYTES + 16384, Ab, Bb, K, p << 5, tid);
        cp_commit();
    }

    int idx = lane >> 3, lr = lane & 7;
    int s = 0;
    for (int it = 0; it < nch; it++) {
        uint32_t sA = sbase + s * STG_BYTES;
        uint32_t sB = sA + 16384;
        cp_wait2();
        __syncthreads();
        #pragma unroll
        for (int ks = 0; ks < 4; ks++) {
            uint32_t a[2][4], b[4][4];
            #pragma unroll
            for (int mf = 0; mf < 2; mf++) {
                int m = (wm << 5) + (mf << 4) + ((idx & 1) << 3) + lr;
                int u = (ks << 1) + (idx >> 1);
                uint32_t ad = sA + (uint32_t)(m << 7) + (((u ^ (m & 7))) << 4);
                LDSM4(a[mf][0], a[mf][1], a[mf][2], a[mf][3], ad);
            }
            #pragma unroll
            for (int g = 0; g < 4; g++) {
                int n = (wn << 6) + (g << 4) + ((idx >> 1) << 3) + lr;
                int u = (ks << 1) + (idx & 1);
                uint32_t bd = sB + (uint32_t)(n << 7) + (((u ^ (n & 7))) << 4);
                LDSM4(b[g][0], b[g][1], b[g][2], b[g][3], bd);
            }
            #pragma unroll
            for (int mf = 0; mf < 2; mf++) {
                #pragma unroll
                for (int g = 0; g < 4; g++) {
                    MMA8(c[mf][2 * g],     a[mf], b[g][0], b[g][1]);
                    MMA8(c[mf][2 * g + 1], a[mf], b[g][2], b[g][3]);
                }
            }
        }
        __syncthreads();
        if (it + ST < nch)
            gload(sA, sB, Ab, Bb, K, (it + ST) << 5, tid);
        cp_commit();
        s++; if (s == ST) s = 0;
    }

    // ---- epilogue: direct stores from fragments ----
    int lr4 = lane >> 2, lc = (lane & 3) << 1;
    #pragma unroll
    for (int mf = 0; mf < 2; mf++) {
        int r0 = (int)bm + (wm << 5) + (mf << 4) + lr4;
        int rows[2] = { r0, r0 + 8 };
        #pragma unroll
        for (int h = 0; h < 2; h++) {
            int row = rows[h];
            size_t drow;
            if (MODE == 1) drow = (size_t)shifted_row(row);
            else drow = (size_t)row;
            #pragma unroll
            for (int nf = 0; nf < 8; nf++) {
                int col = bn + (wn << 6) + (nf << 3) + lc;
                float vx = c[mf][nf][2 * h]     + bias[col];
                float vy = c[mf][nf][2 * h + 1] + bias[col + 1];
                if (MODE == 2) {
                    vx = tf32r(0.5f * vx * (1.f + erff(vx * 0.70710678118654752f)));
                    vy = tf32r(0.5f * vy * (1.f + erff(vy * 0.70710678118654752f)));
                }
                if (MODE == 1) {
                    float2 e = *(const float2*)&extra[drow * 256 + col];
                    vx += e.x; vy += e.y;
                    *(float2*)&C[drow * 256 + col] = make_float2(vx, vy);
                } else if (MODE == 3) {
                    float2 e = *(const float2*)&extra[drow * 256 + col];
                    vx += e.x; vy += e.y;
                    *(float2*)&C[drow * (size_t)N + col] = make_float2(vx, vy);
                } else {
                    *(float2*)&C[drow * (size_t)N + col] = make_float2(vx, vy);
                }
            }
        }
    }
}

// ---------------- windowed attention (fused exp, output tf32-rounded) ----------
__global__ void __launch_bounds__(64)
attn_kernel(const float* __restrict__ q, const float* __restrict__ kv,
            const float* __restrict__ rel, const float* __restrict__ mask,
            float* __restrict__ out) {
    __shared__ float ks[64][36];
    __shared__ float vs[64][36];
    int blk = blockIdx.x;
    int b_ = blk >> 3, head = blk & 7;
    int tid = threadIdx.x;
    int t0 = b_ << 6;

    const float* kvrow = kv + (size_t)(t0 + tid) * 512 + (head << 5);
    #pragma unroll
    for (int d4 = 0; d4 < 8; d4++) {
        *(float4*)&ks[tid][d4 * 4] = *(const float4*)(kvrow + d4 * 4);
        *(float4*)&vs[tid][d4 * 4] = *(const float4*)(kvrow + 256 + d4 * 4);
    }
    float qr[32];
    const float* qrow = q + (size_t)(t0 + tid) * 256 + (head << 5);
    #pragma unroll
    for (int d4 = 0; d4 < 8; d4++) {
        float4 f = *(const float4*)(qrow + d4 * 4);
        qr[d4*4+0] = f.x; qr[d4*4+1] = f.y; qr[d4*4+2] = f.z; qr[d4*4+3] = f.w;
    }
    __syncthreads();

    int i1 = tid >> 3, j1 = tid & 7;
    const float* mrow = mask + ((b_ & 255) << 12) + (tid << 6);
    const float scale = 0.17677669529663687f;

    float accv[32];
    #pragma unroll
    for (int d = 0; d < 32; d++) accv[d] = 0.f;
    float sum = 0.f;
    #pragma unroll
    for (int m = 0; m < 64; m++) {
        float dot = 0.f;
        #pragma unroll
        for (int d4 = 0; d4 < 8; d4++) {
            float4 kf = *(const float4*)&ks[m][d4 * 4];
            dot += qr[d4*4+0]*kf.x + qr[d4*4+1]*kf.y + qr[d4*4+2]*kf.z + qr[d4*4+3]*kf.w;
        }
        int idx = (i1 - (m >> 3) + 7) * 15 + (j1 - (m & 7) + 7);
        float e = __expf(dot * scale + rel[idx * 8 + head] + mrow[m]);
        sum += e;
        #pragma unroll
        for (int d4 = 0; d4 < 8; d4++) {
            float4 vf = *(const float4*)&vs[m][d4 * 4];
            accv[d4*4+0] += e * vf.x; accv[d4*4+1] += e * vf.y;
            accv[d4*4+2] += e * vf.z; accv[d4*4+3] += e * vf.w;
        }
    }
    float inv = 1.f / sum;
    float* orow = out + (size_t)(t0 + tid) * 256 + (head << 5);
    #pragma unroll
    for (int d4 = 0; d4 < 8; d4++)
        *(float4*)(orow + d4 * 4) = make_float4(
            tf32r(accv[d4*4+0]*inv), tf32r(accv[d4*4+1]*inv),
            tf32r(accv[d4*4+2]*inv), tf32r(accv[d4*4+3]*inv));
}

// ---------------- launch -------------------------------------------------------
extern "C" void kernel_launch(void* const* d_in, const int* in_sizes, int n_in,
                              void* d_out, int out_size) {
    (void)in_sizes; (void)n_in; (void)out_size;
    const float* ref  = (const float*)d_in[0];
    const float* adj  = (const float*)d_in[1];
    const float* mask = (const float*)d_in[2];
    const float* n1g = (const float*)d_in[5];
    const float* n1b = (const float*)d_in[6];
    const float* qw  = (const float*)d_in[7];
    const float* qb  = (const float*)d_in[8];
    const float* kvw = (const float*)d_in[9];
    const float* kvb = (const float*)d_in[10];
    const float* rel = (const float*)d_in[11];
    const float* pw  = (const float*)d_in[12];
    const float* pb  = (const float*)d_in[13];
    const float* n2g = (const float*)d_in[14];
    const float* n2b = (const float*)d_in[15];
    const float* f1w = (const float*)d_in[16];
    const float* f1b = (const float*)d_in[17];
    const float* f2w = (const float*)d_in[18];
    const float* f2b = (const float*)d_in[19];
    float* out = (float*)d_out;

    float *rw, *aw, *q, *kv, *ao, *x, *l2, *h, *wt;
    cudaGetSymbolAddress((void**)&rw, g_rw);
    cudaGetSymbolAddress((void**)&aw, g_aw);
    cudaGetSymbolAddress((void**)&q,  g_q);
    cudaGetSymbolAddress((void**)&kv, g_kv);
    cudaGetSymbolAddress((void**)&ao, g_ao);
    cudaGetSymbolAddress((void**)&x,  g_x);
    cudaGetSymbolAddress((void**)&l2, g_l2);
    cudaGetSymbolAddress((void**)&h,  g_h);
    cudaGetSymbolAddress((void**)&wt, g_wt);

    cudaFuncSetAttribute(gemm_mma<0>, cudaFuncAttributeMaxDynamicSharedMemorySize, GEMM_SMEM);
    cudaFuncSetAttribute(gemm_mma<1>, cudaFuncAttributeMaxDynamicSharedMemorySize, GEMM_SMEM);
    cudaFuncSetAttribute(gemm_mma<2>, cudaFuncAttributeMaxDynamicSharedMemorySize, GEMM_SMEM);
    cudaFuncSetAttribute(gemm_mma<3>, cudaFuncAttributeMaxDynamicSharedMemorySize, GEMM_SMEM);

    dim3 tb(32, 8);
    transpose_k<<<dim3(8, 8),  tb>>>(qw,  wt + WT_Q,  256, 256);
    transpose_k<<<dim3(16, 8), tb>>>(kvw, wt + WT_KV, 256, 512);
    transpose_k<<<dim3(8, 8),  tb>>>(pw,  wt + WT_P,  256, 256);
    transpose_k<<<dim3(32, 8), tb>>>(f1w, wt + WT_F1, 256, 1024);
    transpose_k<<<dim3(8, 32), tb>>>(f2w, wt + WT_F2, 1024, 256);

    ln1_kernel<<<TOK, 256>>>(ref, adj, n1g, n1b);
    gemm_mma<0><<<dim3(2, 1024), 256, GEMM_SMEM>>>(rw, wt + WT_Q,  qb,  q,  256, 256,  nullptr);
    gemm_mma<0><<<dim3(4, 1024), 256, GEMM_SMEM>>>(aw, wt + WT_KV, kvb, kv, 256, 512,  nullptr);
    attn_kernel<<<16384, 64>>>(q, kv, rel, mask, ao);
    gemm_mma<1><<<dim3(2, 1024), 256, GEMM_SMEM>>>(ao, wt + WT_P,  pb,  x,  256, 256,  ref);
    ln2_kernel<<<TOK, 256>>>(n2g, n2b);
    gemm_mma<2><<<dim3(8, 1024), 256, GEMM_SMEM>>>(l2, wt + WT_F1, f1b, h,  256, 1024, nullptr);
    gemm_mma<3><<<dim3(2, 1024), 256, GEMM_SMEM>>>(h,  wt + WT_F2, f2b, out, 1024, 256, x);
}

// round 8
// speedup vs baseline: 4.7026x; 1.3258x over previous
#include <cuda_runtime.h>
#include <cuda_bf16.h>
#include <math.h>
#include <stdint.h>

#define TOK 131072
#define CCH 256
#define HID 1024

// fp32 tensors (numerically sensitive)
static __device__ float g_q [(size_t)TOK * CCH];
static __device__ float g_kv[(size_t)TOK * 2 * CCH];
static __device__ float g_x [(size_t)TOK * CCH];
// bf16 tensors (mma operands)
static __device__ __nv_bfloat16 g_rw[(size_t)TOK * CCH];
static __device__ __nv_bfloat16 g_aw[(size_t)TOK * CCH];
static __device__ __nv_bfloat16 g_ao[(size_t)TOK * CCH];
static __device__ __nv_bfloat16 g_l2[(size_t)TOK * CCH];
static __device__ __nv_bfloat16 g_h [(size_t)TOK * HID];
static __device__ __nv_bfloat16 g_wt[786432];
#define WT_Q   0
#define WT_KV  65536
#define WT_P   196608
#define WT_F1  262144
#define WT_F2  524288

// ---------------- helpers ------------------------------------------------------
__device__ __forceinline__ uint32_t smem_u32(const void* p) {
    uint32_t a;
    asm("{ .reg .u64 t; cvta.to.shared.u64 t, %1; cvt.u32.u64 %0, t; }" : "=r"(a) : "l"(p));
    return a;
}
__device__ __forceinline__ void cp16(uint32_t dst, const void* src) {
    asm volatile("cp.async.cg.shared.global [%0], [%1], 16;" :: "r"(dst), "l"(src));
}
__device__ __forceinline__ void cp_commit() { asm volatile("cp.async.commit_group;" ::: "memory"); }
__device__ __forceinline__ void cp_wait3()  { asm volatile("cp.async.wait_group 3;" ::: "memory"); }

#define LDSM4(r0, r1, r2, r3, addr) \
    asm volatile("ldmatrix.sync.aligned.m8n8.x4.shared.b16 {%0,%1,%2,%3}, [%4];" \
        : "=r"(r0), "=r"(r1), "=r"(r2), "=r"(r3) : "r"(addr))

#define MMAB(c, a, b0, b1) \
    asm volatile("mma.sync.aligned.m16n8k16.row.col.f32.bf16.bf16.f32 " \
        "{%0,%1,%2,%3}, {%4,%5,%6,%7}, {%8,%9}, {%0,%1,%2,%3};" \
        : "+f"((c)[0]), "+f"((c)[1]), "+f"((c)[2]), "+f"((c)[3]) \
        : "r"((a)[0]), "r"((a)[1]), "r"((a)[2]), "r"((a)[3]), "r"(b0), "r"(b1))

__device__ __forceinline__ int shifted_row(int t) {
    int b_ = t >> 6, n = t & 63;
    int bi = b_ >> 8, wi = b_ & 255;
    int h = ((((wi >> 4) << 3) | (n >> 3)) + 4) & 127;
    int w = ((((wi & 15) << 3) | (n & 7)) + 4) & 127;
    return (bi << 14) | (h << 7) | w;
}

// ---------------- weight transpose W[K][N] -> Wt[N][K] (bf16) ------------------
__global__ void transpose_k(const float* __restrict__ W, __nv_bfloat16* __restrict__ Wt,
                            int K, int N) {
    __shared__ float t[32][33];
    int n0 = blockIdx.x << 5, k0 = blockIdx.y << 5;
    int tx = threadIdx.x, ty = threadIdx.y;
    #pragma unroll
    for (int j = 0; j < 32; j += 8) t[ty + j][tx] = W[(size_t)(k0 + ty + j) * N + n0 + tx];
    __syncthreads();
    #pragma unroll
    for (int j = 0; j < 32; j += 8)
        Wt[(size_t)(n0 + ty + j) * K + k0 + tx] = __float2bfloat16(t[tx][ty + j]);
}

// ---------------- LayerNorms (bf16 outputs: they feed mma A) -------------------
__device__ __forceinline__ float4 warp_red4(float4 v) {
    #pragma unroll
    for (int o = 16; o > 0; o >>= 1) {
        v.x += __shfl_down_sync(~0u, v.x, o); v.y += __shfl_down_sync(~0u, v.y, o);
        v.z += __shfl_down_sync(~0u, v.z, o); v.w += __shfl_down_sync(~0u, v.w, o);
    }
    return v;
}
__global__ void ln1_kernel(const float* __restrict__ ref, const float* __restrict__ adj,
                           const float* __restrict__ g, const float* __restrict__ b) {
    int t = blockIdx.x, c = threadIdx.x;
    int src = shifted_row(t) * 256 + c;
    float xr = ref[src], xa = adj[src];
    float4 v = warp_red4(make_float4(xr, xr * xr, xa, xa * xa));
    __shared__ float4 red[8]; __shared__ float4 st;
    if (!(c & 31)) red[c >> 5] = v;
    __syncthreads();
    if (c == 0) {
        float4 a = red[0];
        #pragma unroll
        for (int i = 1; i < 8; i++) { a.x += red[i].x; a.y += red[i].y; a.z += red[i].z; a.w += red[i].w; }
        float mr = a.x * (1.f/256.f), ma = a.z * (1.f/256.f);
        st = make_float4(mr, rsqrtf(a.y*(1.f/256.f) - mr*mr + 1e-5f),
                         ma, rsqrtf(a.w*(1.f/256.f) - ma*ma + 1e-5f));
    }
    __syncthreads();
    float4 s = st; int o = t * 256 + c;
    float gc = g[c], bc = b[c];
    g_rw[o] = __float2bfloat16((xr - s.x) * s.y * gc + bc);
    g_aw[o] = __float2bfloat16((xa - s.z) * s.w * gc + bc);
}
__global__ void ln2_kernel(const float* __restrict__ g, const float* __restrict__ b) {
    int t = blockIdx.x, c = threadIdx.x;
    float x = g_x[t * 256 + c];
    float4 v = warp_red4(make_float4(x, x * x, 0.f, 0.f));
    __shared__ float4 red[8]; __shared__ float2 st;
    if (!(c & 31)) red[c >> 5] = v;
    __syncthreads();
    if (c == 0) {
        float sx = 0.f, sxx = 0.f;
        #pragma unroll
        for (int i = 0; i < 8; i++) { sx += red[i].x; sxx += red[i].y; }
        float m = sx * (1.f/256.f);
        st = make_float2(m, rsqrtf(sxx*(1.f/256.f) - m*m + 1e-5f));
    }
    __syncthreads();
    float2 s = st;
    g_l2[t * 256 + c] = __float2bfloat16((x - s.x) * s.y * g[c] + b[c]);
}

// ---------------- bf16 mma.sync GEMM: BM=128, BN=128, BK=32, 4-stage -----------
// smem row = 32 bf16 = 64B stored at 80B pitch -> (5r+u)%8 permutation =>
// conflict-free ldmatrix with no XOR swizzle.
#define ST 4
#define TILE_B 10240          // 128 rows * 80B
#define STG_BYTES 20480
#define GEMM_SMEM (ST * STG_BYTES)   // 80 KB

__device__ __forceinline__ void gload(uint32_t sA,
        const __nv_bfloat16* Ab, const __nv_bfloat16* Bb, int K, int k0, int tid) {
    uint32_t sB = sA + TILE_B;
    #pragma unroll
    for (int i = 0; i < 2; i++) {
        int id = tid + (i << 8);          // 0..511
        int r = id >> 2, u = id & 3;      // row 0..127, 16B unit 0..3
        uint32_t off = (uint32_t)r * 80 + (u << 4);
        cp16(sA + off, Ab + (size_t)r * K + k0 + (u << 3));
        cp16(sB + off, Bb + (size_t)r * K + k0 + (u << 3));
    }
}

// MODE 0: C=AB+bias (f32)  1: proj scatter+residual (f32)
// MODE 2: gelu -> bf16     3: +extra (f32, final out)
template <int MODE>
__global__ void __launch_bounds__(256, 2)
gemm_mma(const __nv_bfloat16* __restrict__ A, const __nv_bfloat16* __restrict__ Bt,
         const float* __restrict__ bias, float* __restrict__ C,
         int K, int N, const float* __restrict__ extra) {
    extern __shared__ __align__(128) char smem[];
    uint32_t sbase = smem_u32(smem);
    int tid = threadIdx.x;
    int lane = tid & 31, wid = tid >> 5;
    int wm = wid & 3, wn = wid >> 2;
    size_t bm = (size_t)blockIdx.y << 7;
    int bn = blockIdx.x << 7;

    const __nv_bfloat16* Ab = A + bm * K;
    const __nv_bfloat16* Bb = Bt + (size_t)bn * K;
    int nch = K >> 5;

    float c[2][8][4];
    #pragma unroll
    for (int i = 0; i < 2; i++)
        #pragma unroll
        for (int j = 0; j < 8; j++)
            #pragma unroll
            for (int k = 0; k < 4; k++) c[i][j][k] = 0.f;

    for (int p = 0; p < ST; p++) {
        gload(sbase + p * STG_BYTES, Ab, Bb, K, p << 5, tid);
        cp_commit();
    }

    int s = 0;
    for (int it = 0; it < nch; it++) {
        uint32_t sA = sbase + s * STG_BYTES;
        uint32_t sB = sA + TILE_B;
        cp_wait3();
        __syncthreads();
        #pragma unroll
        for (int kc = 0; kc < 2; kc++) {
            uint32_t a[2][4], b[4][4];
            #pragma unroll
            for (int mf = 0; mf < 2; mf++) {
                int row = (wm << 5) + (mf << 4) + (lane & 7) + (((lane >> 3) & 1) << 3);
                int u = (kc << 1) + (lane >> 4);
                LDSM4(a[mf][0], a[mf][1], a[mf][2], a[mf][3],
                      sA + (uint32_t)row * 80 + (u << 4));
            }
            #pragma unroll
            for (int g = 0; g < 4; g++) {
                int row = (wn << 6) + (g << 4) + (lane & 7) + ((lane >> 4) << 3);
                int u = (kc << 1) + ((lane >> 3) & 1);
                LDSM4(b[g][0], b[g][1], b[g][2], b[g][3],
                      sB + (uint32_t)row * 80 + (u << 4));
            }
            #pragma unroll
            for (int mf = 0; mf < 2; mf++) {
                #pragma unroll
                for (int g = 0; g < 4; g++) {
                    MMAB(c[mf][2 * g],     a[mf], b[g][0], b[g][1]);
                    MMAB(c[mf][2 * g + 1], a[mf], b[g][2], b[g][3]);
                }
            }
        }
        __syncthreads();
        if (it + ST < nch)
            gload(sA, Ab, Bb, K, (it + ST) << 5, tid);
        cp_commit();
        s++; if (s == ST) s = 0;
    }

    // ---- epilogue: direct stores from fragments ----
    int lr4 = lane >> 2, lc = (lane & 3) << 1;
    #pragma unroll
    for (int mf = 0; mf < 2; mf++) {
        int r0 = (int)bm + (wm << 5) + (mf << 4) + lr4;
        #pragma unroll
        for (int h = 0; h < 2; h++) {
            int row = r0 + (h << 3);
            size_t drow;
            if (MODE == 1) drow = (size_t)shifted_row(row);
            else drow = (size_t)row;
            #pragma unroll
            for (int nf = 0; nf < 8; nf++) {
                int col = bn + (wn << 6) + (nf << 3) + lc;
                float vx = c[mf][nf][2 * h]     + bias[col];
                float vy = c[mf][nf][2 * h + 1] + bias[col + 1];
                if (MODE == 2) {
                    vx = 0.5f * vx * (1.f + erff(vx * 0.70710678118654752f));
                    vy = 0.5f * vy * (1.f + erff(vy * 0.70710678118654752f));
                    __nv_bfloat16* Cb = (__nv_bfloat16*)C;
                    *(__nv_bfloat162*)&Cb[drow * (size_t)N + col] =
                        __floats2bfloat162_rn(vx, vy);
                } else if (MODE == 1) {
                    float2 e = *(const float2*)&extra[drow * 256 + col];
                    vx += e.x; vy += e.y;
                    *(float2*)&C[drow * 256 + col] = make_float2(vx, vy);
                } else if (MODE == 3) {
                    float2 e = *(const float2*)&extra[drow * 256 + col];
                    vx += e.x; vy += e.y;
                    *(float2*)&C[drow * (size_t)N + col] = make_float2(vx, vy);
                } else {
                    *(float2*)&C[drow * (size_t)N + col] = make_float2(vx, vy);
                }
            }
        }
    }
}

// ---------------- windowed attention (fused exp; writes bf16) ------------------
__global__ void __launch_bounds__(64)
attn_kernel(const float* __restrict__ q, const float* __restrict__ kv,
            const float* __restrict__ rel, const float* __restrict__ mask,
            __nv_bfloat16* __restrict__ out) {
    __shared__ float ks[64][36];
    __shared__ float vs[64][36];
    int blk = blockIdx.x;
    int b_ = blk >> 3, head = blk & 7;
    int tid = threadIdx.x;
    int t0 = b_ << 6;

    const float* kvrow = kv + (size_t)(t0 + tid) * 512 + (head << 5);
    #pragma unroll
    for (int d4 = 0; d4 < 8; d4++) {
        *(float4*)&ks[tid][d4 * 4] = *(const float4*)(kvrow + d4 * 4);
        *(float4*)&vs[tid][d4 * 4] = *(const float4*)(kvrow + 256 + d4 * 4);
    }
    float qr[32];
    const float* qrow = q + (size_t)(t0 + tid) * 256 + (head << 5);
    #pragma unroll
    for (int d4 = 0; d4 < 8; d4++) {
        float4 f = *(const float4*)(qrow + d4 * 4);
        qr[d4*4+0] = f.x; qr[d4*4+1] = f.y; qr[d4*4+2] = f.z; qr[d4*4+3] = f.w;
    }
    __syncthreads();

    int i1 = tid >> 3, j1 = tid & 7;
    const float* mrow = mask + ((b_ & 255) << 12) + (tid << 6);
    const float scale = 0.17677669529663687f;

    float accv[32];
    #pragma unroll
    for (int d = 0; d < 32; d++) accv[d] = 0.f;
    float sum = 0.f;
    #pragma unroll
    for (int m = 0; m < 64; m++) {
        float dot = 0.f;
        #pragma unroll
        for (int d4 = 0; d4 < 8; d4++) {
            float4 kf = *(const float4*)&ks[m][d4 * 4];
            dot += qr[d4*4+0]*kf.x + qr[d4*4+1]*kf.y + qr[d4*4+2]*kf.z + qr[d4*4+3]*kf.w;
        }
        int idx = (i1 - (m >> 3) + 7) * 15 + (j1 - (m & 7) + 7);
        float e = __expf(dot * scale + rel[idx * 8 + head] + mrow[m]);
        sum += e;
        #pragma unroll
        for (int d4 = 0; d4 < 8; d4++) {
            float4 vf = *(const float4*)&vs[m][d4 * 4];
            accv[d4*4+0] += e * vf.x; accv[d4*4+1] += e * vf.y;
            accv[d4*4+2] += e * vf.z; accv[d4*4+3] += e * vf.w;
        }
    }
    float inv = 1.f / sum;
    __nv_bfloat16* orow = out + (size_t)(t0 + tid) * 256 + (head << 5);
    #pragma unroll
    for (int i = 0; i < 16; i++)
        *(__nv_bfloat162*)&orow[2 * i] =
            __floats2bfloat162_rn(accv[2*i] * inv, accv[2*i+1] * inv);
}

// ---------------- launch -------------------------------------------------------
extern "C" void kernel_launch(void* const* d_in, const int* in_sizes, int n_in,
                              void* d_out, int out_size) {
    (void)in_sizes; (void)n_in; (void)out_size;
    const float* ref  = (const float*)d_in[0];
    const float* adj  = (const float*)d_in[1];
    const float* mask = (const float*)d_in[2];
    const float* n1g = (const float*)d_in[5];
    const float* n1b = (const float*)d_in[6];
    const float* qw  = (const float*)d_in[7];
    const float* qb  = (const float*)d_in[8];
    const float* kvw = (const float*)d_in[9];
    const float* kvb = (const float*)d_in[10];
    const float* rel = (const float*)d_in[11];
    const float* pw  = (const float*)d_in[12];
    const float* pb  = (const float*)d_in[13];
    const float* n2g = (const float*)d_in[14];
    const float* n2b = (const float*)d_in[15];
    const float* f1w = (const float*)d_in[16];
    const float* f1b = (const float*)d_in[17];
    const float* f2w = (const float*)d_in[18];
    const float* f2b = (const float*)d_in[19];
    float* out = (float*)d_out;

    float *q, *kv, *x;
    __nv_bfloat16 *rw, *aw, *ao, *l2, *h, *wt;
    cudaGetSymbolAddress((void**)&q,  g_q);
    cudaGetSymbolAddress((void**)&kv, g_kv);
    cudaGetSymbolAddress((void**)&x,  g_x);
    cudaGetSymbolAddress((void**)&rw, g_rw);
    cudaGetSymbolAddress((void**)&aw, g_aw);
    cudaGetSymbolAddress((void**)&ao, g_ao);
    cudaGetSymbolAddress((void**)&l2, g_l2);
    cudaGetSymbolAddress((void**)&h,  g_h);
    cudaGetSymbolAddress((void**)&wt, g_wt);

    cudaFuncSetAttribute(gemm_mma<0>, cudaFuncAttributeMaxDynamicSharedMemorySize, GEMM_SMEM);
    cudaFuncSetAttribute(gemm_mma<1>, cudaFuncAttributeMaxDynamicSharedMemorySize, GEMM_SMEM);
    cudaFuncSetAttribute(gemm_mma<2>, cudaFuncAttributeMaxDynamicSharedMemorySize, GEMM_SMEM);
    cudaFuncSetAttribute(gemm_mma<3>, cudaFuncAttributeMaxDynamicSharedMemorySize, GEMM_SMEM);

    dim3 tb(32, 8);
    transpose_k<<<dim3(8, 8),  tb>>>(qw,  wt + WT_Q,  256, 256);
    transpose_k<<<dim3(16, 8), tb>>>(kvw, wt + WT_KV, 256, 512);
    transpose_k<<<dim3(8, 8),  tb>>>(pw,  wt + WT_P,  256, 256);
    transpose_k<<<dim3(32, 8), tb>>>(f1w, wt + WT_F1, 256, 1024);
    transpose_k<<<dim3(8, 32), tb>>>(f2w, wt + WT_F2, 1024, 256);

    ln1_kernel<<<TOK, 256>>>(ref, adj, n1g, n1b);
    gemm_mma<0><<<dim3(2, 1024), 256, GEMM_SMEM>>>(rw, wt + WT_Q,  qb,  q,  256, 256,  nullptr);
    gemm_mma<0><<<dim3(4, 1024), 256, GEMM_SMEM>>>(aw, wt + WT_KV, kvb, kv, 256, 512,  nullptr);
    attn_kernel<<<16384, 64>>>(q, kv, rel, mask, ao);
    gemm_mma<1><<<dim3(2, 1024), 256, GEMM_SMEM>>>(ao, wt + WT_P,  pb,  x,  256, 256,  ref);
    ln2_kernel<<<TOK, 256>>>(n2g, n2b);
    gemm_mma<2><<<dim3(8, 1024), 256, GEMM_SMEM>>>(l2, wt + WT_F1, f1b, (float*)h, 256, 1024, nullptr);
    gemm_mma<3><<<dim3(2, 1024), 256, GEMM_SMEM>>>(h,  wt + WT_F2, f2b, out, 1024, 256, x);
}

// round 9
// speedup vs baseline: 4.9478x; 1.0521x over previous
#include <cuda_runtime.h>
#include <cuda_bf16.h>
#include <math.h>
#include <stdint.h>

#define TOK 131072
#define CCH 256
#define HID 1024

// fp32 tensors (numerically sensitive)
static __device__ float g_q [(size_t)TOK * CCH];
static __device__ float g_kv[(size_t)TOK * 2 * CCH];
static __device__ float g_x [(size_t)TOK * CCH];
// bf16 tensors (mma operands)
static __device__ __nv_bfloat16 g_rw[(size_t)TOK * CCH];
static __device__ __nv_bfloat16 g_aw[(size_t)TOK * CCH];
static __device__ __nv_bfloat16 g_ao[(size_t)TOK * CCH];
static __device__ __nv_bfloat16 g_l2[(size_t)TOK * CCH];
static __device__ __nv_bfloat16 g_h [(size_t)TOK * HID];
static __device__ __nv_bfloat16 g_wt[786432];
#define WT_Q   0
#define WT_KV  65536
#define WT_P   196608
#define WT_F1  262144
#define WT_F2  524288

// ---------------- helpers ------------------------------------------------------
__device__ __forceinline__ uint32_t smem_u32(const void* p) {
    uint32_t a;
    asm("{ .reg .u64 t; cvta.to.shared.u64 t, %1; cvt.u32.u64 %0, t; }" : "=r"(a) : "l"(p));
    return a;
}
__device__ __forceinline__ void cp16(uint32_t dst, const void* src) {
    asm volatile("cp.async.cg.shared.global [%0], [%1], 16;" :: "r"(dst), "l"(src));
}
__device__ __forceinline__ void cp_commit() { asm volatile("cp.async.commit_group;" ::: "memory"); }
__device__ __forceinline__ void cp_wait3()  { asm volatile("cp.async.wait_group 3;" ::: "memory"); }

#define LDSM4(r0, r1, r2, r3, addr) \
    asm volatile("ldmatrix.sync.aligned.m8n8.x4.shared.b16 {%0,%1,%2,%3}, [%4];" \
        : "=r"(r0), "=r"(r1), "=r"(r2), "=r"(r3) : "r"(addr))

#define MMAB(c, a, b0, b1) \
    asm volatile("mma.sync.aligned.m16n8k16.row.col.f32.bf16.bf16.f32 " \
        "{%0,%1,%2,%3}, {%4,%5,%6,%7}, {%8,%9}, {%0,%1,%2,%3};" \
        : "+f"((c)[0]), "+f"((c)[1]), "+f"((c)[2]), "+f"((c)[3]) \
        : "r"((a)[0]), "r"((a)[1]), "r"((a)[2]), "r"((a)[3]), "r"(b0), "r"(b1))

__device__ __forceinline__ int shifted_row(int t) {
    int b_ = t >> 6, n = t & 63;
    int bi = b_ >> 8, wi = b_ & 255;
    int h = ((((wi >> 4) << 3) | (n >> 3)) + 4) & 127;
    int w = ((((wi & 15) << 3) | (n & 7)) + 4) & 127;
    return (bi << 14) | (h << 7) | w;
}

// ---------------- weight transpose W[K][N] -> Wt[N][K] (bf16) ------------------
__global__ void transpose_k(const float* __restrict__ W, __nv_bfloat16* __restrict__ Wt,
                            int K, int N) {
    __shared__ float t[32][33];
    int n0 = blockIdx.x << 5, k0 = blockIdx.y << 5;
    int tx = threadIdx.x, ty = threadIdx.y;
    #pragma unroll
    for (int j = 0; j < 32; j += 8) t[ty + j][tx] = W[(size_t)(k0 + ty + j) * N + n0 + tx];
    __syncthreads();
    #pragma unroll
    for (int j = 0; j < 32; j += 8)
        Wt[(size_t)(n0 + ty + j) * K + k0 + tx] = __float2bfloat16(t[tx][ty + j]);
}

// ---------------- LayerNorms (bf16 outputs: they feed mma A) -------------------
__device__ __forceinline__ float4 warp_red4(float4 v) {
    #pragma unroll
    for (int o = 16; o > 0; o >>= 1) {
        v.x += __shfl_down_sync(~0u, v.x, o); v.y += __shfl_down_sync(~0u, v.y, o);
        v.z += __shfl_down_sync(~0u, v.z, o); v.w += __shfl_down_sync(~0u, v.w, o);
    }
    return v;
}
__global__ void ln1_kernel(const float* __restrict__ ref, const float* __restrict__ adj,
                           const float* __restrict__ g, const float* __restrict__ b) {
    int t = blockIdx.x, c = threadIdx.x;
    int src = shifted_row(t) * 256 + c;
    float xr = ref[src], xa = adj[src];
    float4 v = warp_red4(make_float4(xr, xr * xr, xa, xa * xa));
    __shared__ float4 red[8]; __shared__ float4 st;
    if (!(c & 31)) red[c >> 5] = v;
    __syncthreads();
    if (c == 0) {
        float4 a = red[0];
        #pragma unroll
        for (int i = 1; i < 8; i++) { a.x += red[i].x; a.y += red[i].y; a.z += red[i].z; a.w += red[i].w; }
        float mr = a.x * (1.f/256.f), ma = a.z * (1.f/256.f);
        st = make_float4(mr, rsqrtf(a.y*(1.f/256.f) - mr*mr + 1e-5f),
                         ma, rsqrtf(a.w*(1.f/256.f) - ma*ma + 1e-5f));
    }
    __syncthreads();
    float4 s = st; int o = t * 256 + c;
    float gc = g[c], bc = b[c];
    g_rw[o] = __float2bfloat16((xr - s.x) * s.y * gc + bc);
    g_aw[o] = __float2bfloat16((xa - s.z) * s.w * gc + bc);
}
__global__ void ln2_kernel(const float* __restrict__ g, const float* __restrict__ b) {
    int t = blockIdx.x, c = threadIdx.x;
    float x = g_x[t * 256 + c];
    float4 v = warp_red4(make_float4(x, x * x, 0.f, 0.f));
    __shared__ float4 red[8]; __shared__ float2 st;
    if (!(c & 31)) red[c >> 5] = v;
    __syncthreads();
    if (c == 0) {
        float sx = 0.f, sxx = 0.f;
        #pragma unroll
        for (int i = 0; i < 8; i++) { sx += red[i].x; sxx += red[i].y; }
        float m = sx * (1.f/256.f);
        st = make_float2(m, rsqrtf(sxx*(1.f/256.f) - m*m + 1e-5f));
    }
    __syncthreads();
    float2 s = st;
    g_l2[t * 256 + c] = __float2bfloat16((x - s.x) * s.y * g[c] + b[c]);
}

// ---------------- bf16 mma.sync GEMM: BM=128, BN=128, BK=32, 4-stage -----------
#define ST 4
#define TILE_B 10240
#define STG_BYTES 20480
#define GEMM_SMEM (ST * STG_BYTES)   // 80 KB

__device__ __forceinline__ void gload(uint32_t sA,
        const __nv_bfloat16* Ab, const __nv_bfloat16* Bb, int K, int k0, int tid) {
    uint32_t sB = sA + TILE_B;
    #pragma unroll
    for (int i = 0; i < 2; i++) {
        int id = tid + (i << 8);
        int r = id >> 2, u = id & 3;
        uint32_t off = (uint32_t)r * 80 + (u << 4);
        cp16(sA + off, Ab + (size_t)r * K + k0 + (u << 3));
        cp16(sB + off, Bb + (size_t)r * K + k0 + (u << 3));
    }
}

// MODE 0: C=AB+bias (f32)  1: proj scatter+residual (f32)
// MODE 2: gelu -> bf16     3: +extra (f32, final out)
template <int MODE>
__global__ void __launch_bounds__(256, 2)
gemm_mma(const __nv_bfloat16* __restrict__ A, const __nv_bfloat16* __restrict__ Bt,
         const float* __restrict__ bias, float* __restrict__ C,
         int K, int N, const float* __restrict__ extra) {
    extern __shared__ __align__(128) char smem[];
    uint32_t sbase = smem_u32(smem);
    int tid = threadIdx.x;
    int lane = tid & 31, wid = tid >> 5;
    int wm = wid & 3, wn = wid >> 2;
    size_t bm = (size_t)blockIdx.y << 7;
    int bn = blockIdx.x << 7;

    const __nv_bfloat16* Ab = A + bm * K;
    const __nv_bfloat16* Bb = Bt + (size_t)bn * K;
    int nch = K >> 5;

    float c[2][8][4];
    #pragma unroll
    for (int i = 0; i < 2; i++)
        #pragma unroll
        for (int j = 0; j < 8; j++)
            #pragma unroll
            for (int k = 0; k < 4; k++) c[i][j][k] = 0.f;

    for (int p = 0; p < ST; p++) {
        gload(sbase + p * STG_BYTES, Ab, Bb, K, p << 5, tid);
        cp_commit();
    }

    int s = 0;
    for (int it = 0; it < nch; it++) {
        uint32_t sA = sbase + s * STG_BYTES;
        uint32_t sB = sA + TILE_B;
        cp_wait3();
        __syncthreads();
        #pragma unroll
        for (int kc = 0; kc < 2; kc++) {
            uint32_t a[2][4], b[4][4];
            #pragma unroll
            for (int mf = 0; mf < 2; mf++) {
                int row = (wm << 5) + (mf << 4) + (lane & 7) + (((lane >> 3) & 1) << 3);
                int u = (kc << 1) + (lane >> 4);
                LDSM4(a[mf][0], a[mf][1], a[mf][2], a[mf][3],
                      sA + (uint32_t)row * 80 + (u << 4));
            }
            #pragma unroll
            for (int g = 0; g < 4; g++) {
                int row = (wn << 6) + (g << 4) + (lane & 7) + ((lane >> 4) << 3);
                int u = (kc << 1) + ((lane >> 3) & 1);
                LDSM4(b[g][0], b[g][1], b[g][2], b[g][3],
                      sB + (uint32_t)row * 80 + (u << 4));
            }
            #pragma unroll
            for (int mf = 0; mf < 2; mf++) {
                #pragma unroll
                for (int g = 0; g < 4; g++) {
                    MMAB(c[mf][2 * g],     a[mf], b[g][0], b[g][1]);
                    MMAB(c[mf][2 * g + 1], a[mf], b[g][2], b[g][3]);
                }
            }
        }
        __syncthreads();
        if (it + ST < nch)
            gload(sA, Ab, Bb, K, (it + ST) << 5, tid);
        cp_commit();
        s++; if (s == ST) s = 0;
    }

    // ---- epilogue ----
    int lr4 = lane >> 2, lc = (lane & 3) << 1;
    #pragma unroll
    for (int mf = 0; mf < 2; mf++) {
        int r0 = (int)bm + (wm << 5) + (mf << 4) + lr4;
        #pragma unroll
        for (int h = 0; h < 2; h++) {
            int row = r0 + (h << 3);
            size_t drow;
            if (MODE == 1) drow = (size_t)shifted_row(row);
            else drow = (size_t)row;
            #pragma unroll
            for (int nf = 0; nf < 8; nf++) {
                int col = bn + (wn << 6) + (nf << 3) + lc;
                float vx = c[mf][nf][2 * h]     + bias[col];
                float vy = c[mf][nf][2 * h + 1] + bias[col + 1];
                if (MODE == 2) {
                    vx = 0.5f * vx * (1.f + erff(vx * 0.70710678118654752f));
                    vy = 0.5f * vy * (1.f + erff(vy * 0.70710678118654752f));
                    __nv_bfloat16* Cb = (__nv_bfloat16*)C;
                    *(__nv_bfloat162*)&Cb[drow * (size_t)N + col] =
                        __floats2bfloat162_rn(vx, vy);
                } else if (MODE == 1) {
                    float2 e = *(const float2*)&extra[drow * 256 + col];
                    vx += e.x; vy += e.y;
                    *(float2*)&C[drow * 256 + col] = make_float2(vx, vy);
                } else if (MODE == 3) {
                    float2 e = *(const float2*)&extra[drow * 256 + col];
                    vx += e.x; vy += e.y;
                    *(float2*)&C[drow * (size_t)N + col] = make_float2(vx, vy);
                } else {
                    *(float2*)&C[drow * (size_t)N + col] = make_float2(vx, vy);
                }
            }
        }
    }
}

// ---------------- windowed attention: 2 threads per query row ------------------
// block = 128 threads = one (window, head); thread (n, half) owns 16 head-dims.
// Partial QK dot completed with one shfl_xor(1); exp/sum redundant on the pair.
__global__ void __launch_bounds__(128)
attn_kernel(const float* __restrict__ q, const float* __restrict__ kv,
            const float* __restrict__ rel, const float* __restrict__ mask,
            __nv_bfloat16* __restrict__ out) {
    __shared__ float ks[64][36];
    __shared__ float vs[64][36];
    int blk = blockIdx.x;
    int b_ = blk >> 3, head = blk & 7;
    int tid = threadIdx.x;
    int n = tid >> 1, half = tid & 1;
    int t0 = b_ << 6;
    int hoff = half << 4;
    int dbase = (head << 5) + hoff;

    // each thread loads its 16 k-dims + 16 v-dims for row n
    const float* kvrow = kv + (size_t)(t0 + n) * 512 + dbase;
    #pragma unroll
    for (int j = 0; j < 4; j++) {
        *(float4*)&ks[n][hoff + 4 * j] = *(const float4*)(kvrow + 4 * j);
        *(float4*)&vs[n][hoff + 4 * j] = *(const float4*)(kvrow + 256 + 4 * j);
    }
    float qr[16];
    const float* qrow = q + (size_t)(t0 + n) * 256 + dbase;
    #pragma unroll
    for (int j = 0; j < 4; j++) {
        float4 f = *(const float4*)(qrow + 4 * j);
        qr[4*j+0] = f.x; qr[4*j+1] = f.y; qr[4*j+2] = f.z; qr[4*j+3] = f.w;
    }
    __syncthreads();

    int i1 = n >> 3, j1 = n & 7;
    const float* mrow = mask + ((b_ & 255) << 12) + (n << 6);
    const float scale = 0.17677669529663687f;

    float accv[16];
    #pragma unroll
    for (int d = 0; d < 16; d++) accv[d] = 0.f;
    float sum = 0.f;
    #pragma unroll 4
    for (int m = 0; m < 64; m++) {
        float dp = 0.f;
        #pragma unroll
        for (int j4 = 0; j4 < 4; j4++) {
            float4 kf = *(const float4*)&ks[m][hoff + 4 * j4];
            dp += qr[4*j4+0]*kf.x + qr[4*j4+1]*kf.y + qr[4*j4+2]*kf.z + qr[4*j4+3]*kf.w;
        }
        float dot = dp + __shfl_xor_sync(~0u, dp, 1);
        int idx = (i1 - (m >> 3) + 7) * 15 + (j1 - (m & 7) + 7);
        float e = __expf(dot * scale + rel[idx * 8 + head] + mrow[m]);
        sum += e;
        #pragma unroll
        for (int j4 = 0; j4 < 4; j4++) {
            float4 vf = *(const float4*)&vs[m][hoff + 4 * j4];
            accv[4*j4+0] += e * vf.x; accv[4*j4+1] += e * vf.y;
            accv[4*j4+2] += e * vf.z; accv[4*j4+3] += e * vf.w;
        }
    }
    float inv = 1.f / sum;
    __nv_bfloat16* orow = out + (size_t)(t0 + n) * 256 + dbase;
    #pragma unroll
    for (int i = 0; i < 8; i++)
        *(__nv_bfloat162*)&orow[2 * i] =
            __floats2bfloat162_rn(accv[2*i] * inv, accv[2*i+1] * inv);
}

// ---------------- launch -------------------------------------------------------
extern "C" void kernel_launch(void* const* d_in, const int* in_sizes, int n_in,
                              void* d_out, int out_size) {
    (void)in_sizes; (void)n_in; (void)out_size;
    const float* ref  = (const float*)d_in[0];
    const float* adj  = (const float*)d_in[1];
    const float* mask = (const float*)d_in[2];
    const float* n1g = (const float*)d_in[5];
    const float* n1b = (const float*)d_in[6];
    const float* qw  = (const float*)d_in[7];
    const float* qb  = (const float*)d_in[8];
    const float* kvw = (const float*)d_in[9];
    const float* kvb = (const float*)d_in[10];
    const float* rel = (const float*)d_in[11];
    const float* pw  = (const float*)d_in[12];
    const float* pb  = (const float*)d_in[13];
    const float* n2g = (const float*)d_in[14];
    const float* n2b = (const float*)d_in[15];
    const float* f1w = (const float*)d_in[16];
    const float* f1b = (const float*)d_in[17];
    const float* f2w = (const float*)d_in[18];
    const float* f2b = (const float*)d_in[19];
    float* out = (float*)d_out;

    float *q, *kv, *x;
    __nv_bfloat16 *rw, *aw, *ao, *l2, *h, *wt;
    cudaGetSymbolAddress((void**)&q,  g_q);
    cudaGetSymbolAddress((void**)&kv, g_kv);
    cudaGetSymbolAddress((void**)&x,  g_x);
    cudaGetSymbolAddress((void**)&rw, g_rw);
    cudaGetSymbolAddress((void**)&aw, g_aw);
    cudaGetSymbolAddress((void**)&ao, g_ao);
    cudaGetSymbolAddress((void**)&l2, g_l2);
    cudaGetSymbolAddress((void**)&h,  g_h);
    cudaGetSymbolAddress((void**)&wt, g_wt);

    cudaFuncSetAttribute(gemm_mma<0>, cudaFuncAttributeMaxDynamicSharedMemorySize, GEMM_SMEM);
    cudaFuncSetAttribute(gemm_mma<1>, cudaFuncAttributeMaxDynamicSharedMemorySize, GEMM_SMEM);
    cudaFuncSetAttribute(gemm_mma<2>, cudaFuncAttributeMaxDynamicSharedMemorySize, GEMM_SMEM);
    cudaFuncSetAttribute(gemm_mma<3>, cudaFuncAttributeMaxDynamicSharedMemorySize, GEMM_SMEM);

    dim3 tb(32, 8);
    transpose_k<<<dim3(8, 8),  tb>>>(qw,  wt + WT_Q,  256, 256);
    transpose_k<<<dim3(16, 8), tb>>>(kvw, wt + WT_KV, 256, 512);
    transpose_k<<<dim3(8, 8),  tb>>>(pw,  wt + WT_P,  256, 256);
    transpose_k<<<dim3(32, 8), tb>>>(f1w, wt + WT_F1, 256, 1024);
    transpose_k<<<dim3(8, 32), tb>>>(f2w, wt + WT_F2, 1024, 256);

    ln1_kernel<<<TOK, 256>>>(ref, adj, n1g, n1b);
    gemm_mma<0><<<dim3(2, 1024), 256, GEMM_SMEM>>>(rw, wt + WT_Q,  qb,  q,  256, 256,  nullptr);
    gemm_mma<0><<<dim3(4, 1024), 256, GEMM_SMEM>>>(aw, wt + WT_KV, kvb, kv, 256, 512,  nullptr);
    attn_kernel<<<16384, 128>>>(q, kv, rel, mask, ao);
    gemm_mma<1><<<dim3(2, 1024), 256, GEMM_SMEM>>>(ao, wt + WT_P,  pb,  x,  256, 256,  ref);
    ln2_kernel<<<TOK, 256>>>(n2g, n2b);
    gemm_mma<2><<<dim3(8, 1024), 256, GEMM_SMEM>>>(l2, wt + WT_F1, f1b, (float*)h, 256, 1024, nullptr);
    gemm_mma<3><<<dim3(2, 1024), 256, GEMM_SMEM>>>(h,  wt + WT_F2, f2b, out, 1024, 256, x);
}

// round 10
// speedup vs baseline: 5.0360x; 1.0178x over previous
#include <cuda_runtime.h>
#include <cuda_bf16.h>
#include <math.h>
#include <stdint.h>

#define TOK 131072
#define CCH 256
#define HID 1024

// fp32 tensors (numerically sensitive)
static __device__ float g_q [(size_t)TOK * CCH];
static __device__ float g_kv[(size_t)TOK * 2 * CCH];
static __device__ float g_x [(size_t)TOK * CCH];
// bf16 tensors (mma operands)
static __device__ __nv_bfloat16 g_rw[(size_t)TOK * CCH];
static __device__ __nv_bfloat16 g_aw[(size_t)TOK * CCH];
static __device__ __nv_bfloat16 g_ao[(size_t)TOK * CCH];
static __device__ __nv_bfloat16 g_l2[(size_t)TOK * CCH];
static __device__ __nv_bfloat16 g_h [(size_t)TOK * HID];
static __device__ __nv_bfloat16 g_wt[786432];
#define WT_Q   0
#define WT_KV  65536
#define WT_P   196608
#define WT_F1  262144
#define WT_F2  524288

// ---------------- helpers ------------------------------------------------------
__device__ __forceinline__ uint32_t smem_u32(const void* p) {
    uint32_t a;
    asm("{ .reg .u64 t; cvta.to.shared.u64 t, %1; cvt.u32.u64 %0, t; }" : "=r"(a) : "l"(p));
    return a;
}
__device__ __forceinline__ void cp16(uint32_t dst, const void* src) {
    asm volatile("cp.async.cg.shared.global [%0], [%1], 16;" :: "r"(dst), "l"(src));
}
__device__ __forceinline__ void cp_commit() { asm volatile("cp.async.commit_group;" ::: "memory"); }
__device__ __forceinline__ void cp_wait2()  { asm volatile("cp.async.wait_group 2;" ::: "memory"); }

#define LDSM4(r0, r1, r2, r3, addr) \
    asm volatile("ldmatrix.sync.aligned.m8n8.x4.shared.b16 {%0,%1,%2,%3}, [%4];" \
        : "=r"(r0), "=r"(r1), "=r"(r2), "=r"(r3) : "r"(addr))

#define MMAB(c, a, b0, b1) \
    asm volatile("mma.sync.aligned.m16n8k16.row.col.f32.bf16.bf16.f32 " \
        "{%0,%1,%2,%3}, {%4,%5,%6,%7}, {%8,%9}, {%0,%1,%2,%3};" \
        : "+f"((c)[0]), "+f"((c)[1]), "+f"((c)[2]), "+f"((c)[3]) \
        : "r"((a)[0]), "r"((a)[1]), "r"((a)[2]), "r"((a)[3]), "r"(b0), "r"(b1))

__device__ __forceinline__ int shifted_row(int t) {
    int b_ = t >> 6, n = t & 63;
    int bi = b_ >> 8, wi = b_ & 255;
    int h = ((((wi >> 4) << 3) | (n >> 3)) + 4) & 127;
    int w = ((((wi & 15) << 3) | (n & 7)) + 4) & 127;
    return (bi << 14) | (h << 7) | w;
}

// ---------------- fused weight transpose (all 5 weights, one launch) -----------
__global__ void transpose_all(const float* __restrict__ qw, const float* __restrict__ kvw,
                              const float* __restrict__ pw, const float* __restrict__ f1w,
                              const float* __restrict__ f2w, __nv_bfloat16* __restrict__ wt) {
    __shared__ float t[32][33];
    int b = blockIdx.x;
    const float* W; __nv_bfloat16* Wt; int K, N, nx, local;
    if (b < 64)       { W = qw;  Wt = wt + WT_Q;  K = 256;  N = 256;  nx = 8;  local = b; }
    else if (b < 192) { W = kvw; Wt = wt + WT_KV; K = 256;  N = 512;  nx = 16; local = b - 64; }
    else if (b < 256) { W = pw;  Wt = wt + WT_P;  K = 256;  N = 256;  nx = 8;  local = b - 192; }
    else if (b < 512) { W = f1w; Wt = wt + WT_F1; K = 256;  N = 1024; nx = 32; local = b - 256; }
    else              { W = f2w; Wt = wt + WT_F2; K = 1024; N = 256;  nx = 8;  local = b - 512; }
    int n0 = (local % nx) << 5, k0 = (local / nx) << 5;
    int tx = threadIdx.x, ty = threadIdx.y;
    #pragma unroll
    for (int j = 0; j < 32; j += 8) t[ty + j][tx] = W[(size_t)(k0 + ty + j) * N + n0 + tx];
    __syncthreads();
    #pragma unroll
    for (int j = 0; j < 32; j += 8)
        Wt[(size_t)(n0 + ty + j) * K + k0 + tx] = __float2bfloat16(t[tx][ty + j]);
}

// ---------------- LayerNorms (bf16 outputs: they feed mma A) -------------------
__device__ __forceinline__ float4 warp_red4(float4 v) {
    #pragma unroll
    for (int o = 16; o > 0; o >>= 1) {
        v.x += __shfl_down_sync(~0u, v.x, o); v.y += __shfl_down_sync(~0u, v.y, o);
        v.z += __shfl_down_sync(~0u, v.z, o); v.w += __shfl_down_sync(~0u, v.w, o);
    }
    return v;
}
__global__ void ln1_kernel(const float* __restrict__ ref, const float* __restrict__ adj,
                           const float* __restrict__ g, const float* __restrict__ b) {
    int t = blockIdx.x, c = threadIdx.x;
    int src = shifted_row(t) * 256 + c;
    float xr = ref[src], xa = adj[src];
    float4 v = warp_red4(make_float4(xr, xr * xr, xa, xa * xa));
    __shared__ float4 red[8]; __shared__ float4 st;
    if (!(c & 31)) red[c >> 5] = v;
    __syncthreads();
    if (c == 0) {
        float4 a = red[0];
        #pragma unroll
        for (int i = 1; i < 8; i++) { a.x += red[i].x; a.y += red[i].y; a.z += red[i].z; a.w += red[i].w; }
        float mr = a.x * (1.f/256.f), ma = a.z * (1.f/256.f);
        st = make_float4(mr, rsqrtf(a.y*(1.f/256.f) - mr*mr + 1e-5f),
                         ma, rsqrtf(a.w*(1.f/256.f) - ma*ma + 1e-5f));
    }
    __syncthreads();
    float4 s = st; int o = t * 256 + c;
    float gc = g[c], bc = b[c];
    g_rw[o] = __float2bfloat16((xr - s.x) * s.y * gc + bc);
    g_aw[o] = __float2bfloat16((xa - s.z) * s.w * gc + bc);
}
__global__ void ln2_kernel(const float* __restrict__ g, const float* __restrict__ b) {
    int t = blockIdx.x, c = threadIdx.x;
    float x = g_x[t * 256 + c];
    float4 v = warp_red4(make_float4(x, x * x, 0.f, 0.f));
    __shared__ float4 red[8]; __shared__ float2 st;
    if (!(c & 31)) red[c >> 5] = v;
    __syncthreads();
    if (c == 0) {
        float sx = 0.f, sxx = 0.f;
        #pragma unroll
        for (int i = 0; i < 8; i++) { sx += red[i].x; sxx += red[i].y; }
        float m = sx * (1.f/256.f);
        st = make_float2(m, rsqrtf(sxx*(1.f/256.f) - m*m + 1e-5f));
    }
    __syncthreads();
    float2 s = st;
    g_l2[t * 256 + c] = __float2bfloat16((x - s.x) * s.y * g[c] + b[c]);
}

// ---------------- bf16 mma.sync GEMM: BM=128, BN=128, BK=32 --------------------
// 4 stages, cutlass-style: one __syncthreads per iteration; loads for chunk
// it+ST-1 go into the stage freed by this iteration's sync.
#define ST 4
#define TILE_B 10240
#define STG_BYTES 20480
#define GEMM_SMEM (ST * STG_BYTES)   // 80 KB

__device__ __forceinline__ void gload(uint32_t sA,
        const __nv_bfloat16* Ab, const __nv_bfloat16* Bb, int K, int k0, int tid) {
    uint32_t sB = sA + TILE_B;
    #pragma unroll
    for (int i = 0; i < 2; i++) {
        int id = tid + (i << 8);
        int r = id >> 2, u = id & 3;
        uint32_t off = (uint32_t)r * 80 + (u << 4);
        cp16(sA + off, Ab + (size_t)r * K + k0 + (u << 3));
        cp16(sB + off, Bb + (size_t)r * K + k0 + (u << 3));
    }
}

// MODE 0: C=AB+bias (f32)  1: proj scatter+residual (f32)
// MODE 2: gelu -> bf16     3: +extra (f32, final out)
template <int MODE>
__global__ void __launch_bounds__(256, 2)
gemm_mma(const __nv_bfloat16* __restrict__ A, const __nv_bfloat16* __restrict__ Bt,
         const float* __restrict__ bias, float* __restrict__ C,
         int K, int N, const float* __restrict__ extra) {
    extern __shared__ __align__(128) char smem[];
    uint32_t sbase = smem_u32(smem);
    int tid = threadIdx.x;
    int lane = tid & 31, wid = tid >> 5;
    int wm = wid & 3, wn = wid >> 2;
    size_t bm = (size_t)blockIdx.y << 7;
    int bn = blockIdx.x << 7;

    const __nv_bfloat16* Ab = A + bm * K;
    const __nv_bfloat16* Bb = Bt + (size_t)bn * K;
    int nch = K >> 5;

    float c[2][8][4];
    #pragma unroll
    for (int i = 0; i < 2; i++)
        #pragma unroll
        for (int j = 0; j < 8; j++)
            #pragma unroll
            for (int k = 0; k < 4; k++) c[i][j][k] = 0.f;

    // prologue: ST-1 stages
    for (int p = 0; p < ST - 1; p++) {
        gload(sbase + p * STG_BYTES, Ab, Bb, K, p << 5, tid);
        cp_commit();
    }

    for (int it = 0; it < nch; it++) {
        cp_wait2();
        __syncthreads();
        // loads for chunk it+ST-1 into the stage freed by this sync
        if (it + ST - 1 < nch)
            gload(sbase + ((it + ST - 1) & (ST - 1)) * STG_BYTES, Ab, Bb, K,
                  (it + ST - 1) << 5, tid);
        cp_commit();

        uint32_t sA = sbase + (it & (ST - 1)) * STG_BYTES;
        uint32_t sB = sA + TILE_B;
        #pragma unroll
        for (int kc = 0; kc < 2; kc++) {
            uint32_t a[2][4], b[4][4];
            #pragma unroll
            for (int mf = 0; mf < 2; mf++) {
                int row = (wm << 5) + (mf << 4) + (lane & 7) + (((lane >> 3) & 1) << 3);
                int u = (kc << 1) + (lane >> 4);
                LDSM4(a[mf][0], a[mf][1], a[mf][2], a[mf][3],
                      sA + (uint32_t)row * 80 + (u << 4));
            }
            #pragma unroll
            for (int g = 0; g < 4; g++) {
                int row = (wn << 6) + (g << 4) + (lane & 7) + ((lane >> 4) << 3);
                int u = (kc << 1) + ((lane >> 3) & 1);
                LDSM4(b[g][0], b[g][1], b[g][2], b[g][3],
                      sB + (uint32_t)row * 80 + (u << 4));
            }
            #pragma unroll
            for (int mf = 0; mf < 2; mf++) {
                #pragma unroll
                for (int g = 0; g < 4; g++) {
                    MMAB(c[mf][2 * g],     a[mf], b[g][0], b[g][1]);
                    MMAB(c[mf][2 * g + 1], a[mf], b[g][2], b[g][3]);
                }
            }
        }
    }

    // ---- epilogue ----
    int lr4 = lane >> 2, lc = (lane & 3) << 1;
    #pragma unroll
    for (int mf = 0; mf < 2; mf++) {
        int r0 = (int)bm + (wm << 5) + (mf << 4) + lr4;
        #pragma unroll
        for (int h = 0; h < 2; h++) {
            int row = r0 + (h << 3);
            size_t drow;
            if (MODE == 1) drow = (size_t)shifted_row(row);
            else drow = (size_t)row;
            #pragma unroll
            for (int nf = 0; nf < 8; nf++) {
                int col = bn + (wn << 6) + (nf << 3) + lc;
                float vx = c[mf][nf][2 * h]     + bias[col];
                float vy = c[mf][nf][2 * h + 1] + bias[col + 1];
                if (MODE == 2) {
                    vx = 0.5f * vx * (1.f + erff(vx * 0.70710678118654752f));
                    vy = 0.5f * vy * (1.f + erff(vy * 0.70710678118654752f));
                    __nv_bfloat16* Cb = (__nv_bfloat16*)C;
                    *(__nv_bfloat162*)&Cb[drow * (size_t)N + col] =
                        __floats2bfloat162_rn(vx, vy);
                } else if (MODE == 1) {
                    float2 e = *(const float2*)&extra[drow * 256 + col];
                    vx += e.x; vy += e.y;
                    *(float2*)&C[drow * 256 + col] = make_float2(vx, vy);
                } else if (MODE == 3) {
                    float2 e = *(const float2*)&extra[drow * 256 + col];
                    vx += e.x; vy += e.y;
                    *(float2*)&C[drow * (size_t)N + col] = make_float2(vx, vy);
                } else {
                    *(float2*)&C[drow * (size_t)N + col] = make_float2(vx, vy);
                }
            }
        }
    }
}

// ---------------- windowed attention: 2 threads per query row ------------------
__global__ void __launch_bounds__(128)
attn_kernel(const float* __restrict__ q, const float* __restrict__ kv,
            const float* __restrict__ rel, const float* __restrict__ mask,
            __nv_bfloat16* __restrict__ out) {
    __shared__ float ks[64][36];
    __shared__ float vs[64][36];
    int blk = blockIdx.x;
    int b_ = blk >> 3, head = blk & 7;
    int tid = threadIdx.x;
    int n = tid >> 1, half = tid & 1;
    int t0 = b_ << 6;
    int hoff = half << 4;
    int dbase = (head << 5) + hoff;

    const float* kvrow = kv + (size_t)(t0 + n) * 512 + dbase;
    #pragma unroll
    for (int j = 0; j < 4; j++) {
        *(float4*)&ks[n][hoff + 4 * j] = *(const float4*)(kvrow + 4 * j);
        *(float4*)&vs[n][hoff + 4 * j] = *(const float4*)(kvrow + 256 + 4 * j);
    }
    float qr[16];
    const float* qrow = q + (size_t)(t0 + n) * 256 + dbase;
    #pragma unroll
    for (int j = 0; j < 4; j++) {
        float4 f = *(const float4*)(qrow + 4 * j);
        qr[4*j+0] = f.x; qr[4*j+1] = f.y; qr[4*j+2] = f.z; qr[4*j+3] = f.w;
    }
    __syncthreads();

    int i1 = n >> 3, j1 = n & 7;
    const float* mrow = mask + ((b_ & 255) << 12) + (n << 6);
    const float scale = 0.17677669529663687f;

    float accv[16];
    #pragma unroll
    for (int d = 0; d < 16; d++) accv[d] = 0.f;
    float sum = 0.f;
    #pragma unroll 4
    for (int m = 0; m < 64; m++) {
        float dp = 0.f;
        #pragma unroll
        for (int j4 = 0; j4 < 4; j4++) {
            float4 kf = *(const float4*)&ks[m][hoff + 4 * j4];
            dp += qr[4*j4+0]*kf.x + qr[4*j4+1]*kf.y + qr[4*j4+2]*kf.z + qr[4*j4+3]*kf.w;
        }
        float dot = dp + __shfl_xor_sync(~0u, dp, 1);
        int idx = (i1 - (m >> 3) + 7) * 15 + (j1 - (m & 7) + 7);
        float e = __expf(dot * scale + rel[idx * 8 + head] + mrow[m]);
        sum += e;
        #pragma unroll
        for (int j4 = 0; j4 < 4; j4++) {
            float4 vf = *(const float4*)&vs[m][hoff + 4 * j4];
            accv[4*j4+0] += e * vf.x; accv[4*j4+1] += e * vf.y;
            accv[4*j4+2] += e * vf.z; accv[4*j4+3] += e * vf.w;
        }
    }
    float inv = 1.f / sum;
    __nv_bfloat16* orow = out + (size_t)(t0 + n) * 256 + dbase;
    #pragma unroll
    for (int i = 0; i < 8; i++)
        *(__nv_bfloat162*)&orow[2 * i] =
            __floats2bfloat162_rn(accv[2*i] * inv, accv[2*i+1] * inv);
}

// ---------------- launch -------------------------------------------------------
extern "C" void kernel_launch(void* const* d_in, const int* in_sizes, int n_in,
                              void* d_out, int out_size) {
    (void)in_sizes; (void)n_in; (void)out_size;
    const float* ref  = (const float*)d_in[0];
    const float* adj  = (const float*)d_in[1];
    const float* mask = (const float*)d_in[2];
    const float* n1g = (const float*)d_in[5];
    const float* n1b = (const float*)d_in[6];
    const float* qw  = (const float*)d_in[7];
    const float* qb  = (const float*)d_in[8];
    const float* kvw = (const float*)d_in[9];
    const float* kvb = (const float*)d_in[10];
    const float* rel = (const float*)d_in[11];
    const float* pw  = (const float*)d_in[12];
    const float* pb  = (const float*)d_in[13];
    const float* n2g = (const float*)d_in[14];
    const float* n2b = (const float*)d_in[15];
    const float* f1w = (const float*)d_in[16];
    const float* f1b = (const float*)d_in[17];
    const float* f2w = (const float*)d_in[18];
    const float* f2b = (const float*)d_in[19];
    float* out = (float*)d_out;

    float *q, *kv, *x;
    __nv_bfloat16 *rw, *aw, *ao, *l2, *h, *wt;
    cudaGetSymbolAddress((void**)&q,  g_q);
    cudaGetSymbolAddress((void**)&kv, g_kv);
    cudaGetSymbolAddress((void**)&x,  g_x);
    cudaGetSymbolAddress((void**)&rw, g_rw);
    cudaGetSymbolAddress((void**)&aw, g_aw);
    cudaGetSymbolAddress((void**)&ao, g_ao);
    cudaGetSymbolAddress((void**)&l2, g_l2);
    cudaGetSymbolAddress((void**)&h,  g_h);
    cudaGetSymbolAddress((void**)&wt, g_wt);

    cudaFuncSetAttribute(gemm_mma<0>, cudaFuncAttributeMaxDynamicSharedMemorySize, GEMM_SMEM);
    cudaFuncSetAttribute(gemm_mma<1>, cudaFuncAttributeMaxDynamicSharedMemorySize, GEMM_SMEM);
    cudaFuncSetAttribute(gemm_mma<2>, cudaFuncAttributeMaxDynamicSharedMemorySize, GEMM_SMEM);
    cudaFuncSetAttribute(gemm_mma<3>, cudaFuncAttributeMaxDynamicSharedMemorySize, GEMM_SMEM);

    transpose_all<<<768, dim3(32, 8)>>>(qw, kvw, pw, f1w, f2w, wt);
    ln1_kernel<<<TOK, 256>>>(ref, adj, n1g, n1b);
    gemm_mma<0><<<dim3(2, 1024), 256, GEMM_SMEM>>>(rw, wt + WT_Q,  qb,  q,  256, 256,  nullptr);
    gemm_mma<0><<<dim3(4, 1024), 256, GEMM_SMEM>>>(aw, wt + WT_KV, kvb, kv, 256, 512,  nullptr);
    attn_kernel<<<16384, 128>>>(q, kv, rel, mask, ao);
    gemm_mma<1><<<dim3(2, 1024), 256, GEMM_SMEM>>>(ao, wt + WT_P,  pb,  x,  256, 256,  ref);
    ln2_kernel<<<TOK, 256>>>(n2g, n2b);
    gemm_mma<2><<<dim3(8, 1024), 256, GEMM_SMEM>>>(l2, wt + WT_F1, f1b, (float*)h, 256, 1024, nullptr);
    gemm_mma<3><<<dim3(2, 1024), 256, GEMM_SMEM>>>(h,  wt + WT_F2, f2b, out, 1024, 256, x);
}

// round 11
// speedup vs baseline: 5.5201x; 1.0961x over previous
#include <cuda_runtime.h>
#include <cuda_bf16.h>
#include <math.h>
#include <stdint.h>

#define TOK 131072
#define CCH 256
#define HID 1024

// fp32 (numerically sensitive)
static __device__ float g_x [(size_t)TOK * CCH];
static __device__ float g_cmb[2048 * 4096];          // bias+mask, [combo][m][n]
// bf16 (mma / attention operands)
static __device__ __nv_bfloat16 g_q [(size_t)TOK * CCH];
static __device__ __nv_bfloat16 g_kv[(size_t)TOK * 2 * CCH];
static __device__ __nv_bfloat16 g_rw[(size_t)TOK * CCH];
static __device__ __nv_bfloat16 g_aw[(size_t)TOK * CCH];
static __device__ __nv_bfloat16 g_ao[(size_t)TOK * CCH];
static __device__ __nv_bfloat16 g_l2[(size_t)TOK * CCH];
static __device__ __nv_bfloat16 g_h [(size_t)TOK * HID];
static __device__ __nv_bfloat16 g_wt[786432];
#define WT_Q   0
#define WT_KV  65536
#define WT_P   196608
#define WT_F1  262144
#define WT_F2  524288

// ---------------- helpers ------------------------------------------------------
__device__ __forceinline__ uint32_t smem_u32(const void* p) {
    uint32_t a;
    asm("{ .reg .u64 t; cvta.to.shared.u64 t, %1; cvt.u32.u64 %0, t; }" : "=r"(a) : "l"(p));
    return a;
}
__device__ __forceinline__ void cp16(uint32_t dst, const void* src) {
    asm volatile("cp.async.cg.shared.global [%0], [%1], 16;" :: "r"(dst), "l"(src));
}
__device__ __forceinline__ void cp_commit() { asm volatile("cp.async.commit_group;" ::: "memory"); }
__device__ __forceinline__ void cp_wait3()  { asm volatile("cp.async.wait_group 3;" ::: "memory"); }

#define LDSM4(r0, r1, r2, r3, addr) \
    asm volatile("ldmatrix.sync.aligned.m8n8.x4.shared.b16 {%0,%1,%2,%3}, [%4];" \
        : "=r"(r0), "=r"(r1), "=r"(r2), "=r"(r3) : "r"(addr))

#define MMAB(c, a, b0, b1) \
    asm volatile("mma.sync.aligned.m16n8k16.row.col.f32.bf16.bf16.f32 " \
        "{%0,%1,%2,%3}, {%4,%5,%6,%7}, {%8,%9}, {%0,%1,%2,%3};" \
        : "+f"((c)[0]), "+f"((c)[1]), "+f"((c)[2]), "+f"((c)[3]) \
        : "r"((a)[0]), "r"((a)[1]), "r"((a)[2]), "r"((a)[3]), "r"(b0), "r"(b1))

__device__ __forceinline__ int shifted_row(int t) {
    int b_ = t >> 6, n = t & 63;
    int bi = b_ >> 8, wi = b_ & 255;
    int h = ((((wi >> 4) << 3) | (n >> 3)) + 4) & 127;
    int w = ((((wi & 15) << 3) | (n & 7)) + 4) & 127;
    return (bi << 14) | (h << 7) | w;
}

// ---------------- fused weight transpose ---------------------------------------
__global__ void transpose_all(const float* __restrict__ qw, const float* __restrict__ kvw,
                              const float* __restrict__ pw, const float* __restrict__ f1w,
                              const float* __restrict__ f2w, __nv_bfloat16* __restrict__ wt) {
    __shared__ float t[32][33];
    int b = blockIdx.x;
    const float* W; __nv_bfloat16* Wt; int K, N, nx, local;
    if (b < 64)       { W = qw;  Wt = wt + WT_Q;  K = 256;  N = 256;  nx = 8;  local = b; }
    else if (b < 192) { W = kvw; Wt = wt + WT_KV; K = 256;  N = 512;  nx = 16; local = b - 64; }
    else if (b < 256) { W = pw;  Wt = wt + WT_P;  K = 256;  N = 256;  nx = 8;  local = b - 192; }
    else if (b < 512) { W = f1w; Wt = wt + WT_F1; K = 256;  N = 1024; nx = 32; local = b - 256; }
    else              { W = f2w; Wt = wt + WT_F2; K = 1024; N = 256;  nx = 8;  local = b - 512; }
    int n0 = (local % nx) << 5, k0 = (local / nx) << 5;
    int tx = threadIdx.x, ty = threadIdx.y;
    #pragma unroll
    for (int j = 0; j < 32; j += 8) t[ty + j][tx] = W[(size_t)(k0 + ty + j) * N + n0 + tx];
    __syncthreads();
    #pragma unroll
    for (int j = 0; j < 32; j += 8)
        Wt[(size_t)(n0 + ty + j) * K + k0 + tx] = __float2bfloat16(t[tx][ty + j]);
}

// ---------------- bias+mask precombine: cmb[combo][m][n] -----------------------
__global__ void build_cmb(const float* __restrict__ rel, const float* __restrict__ mask,
                          float* __restrict__ cmb) {
    int combo = blockIdx.x;            // win*8 + head
    int win = combo >> 3, head = combo & 7;
    const float* mwin = mask + win * 4096;
    float* dst = cmb + (size_t)combo * 4096;
    for (int id = threadIdx.x; id < 4096; id += 256) {
        int m = id >> 6, n = id & 63;
        int idx = ((n >> 3) - (m >> 3) + 7) * 15 + ((n & 7) - (m & 7) + 7);
        dst[id] = rel[idx * 8 + head] + mwin[n * 64 + m];
    }
}

// ---------------- LayerNorms ---------------------------------------------------
__device__ __forceinline__ float4 warp_red4(float4 v) {
    #pragma unroll
    for (int o = 16; o > 0; o >>= 1) {
        v.x += __shfl_down_sync(~0u, v.x, o); v.y += __shfl_down_sync(~0u, v.y, o);
        v.z += __shfl_down_sync(~0u, v.z, o); v.w += __shfl_down_sync(~0u, v.w, o);
    }
    return v;
}
__global__ void ln1_kernel(const float* __restrict__ ref, const float* __restrict__ adj,
                           const float* __restrict__ g, const float* __restrict__ b) {
    int t = blockIdx.x, c = threadIdx.x;
    int src = shifted_row(t) * 256 + c;
    float xr = ref[src], xa = adj[src];
    float4 v = warp_red4(make_float4(xr, xr * xr, xa, xa * xa));
    __shared__ float4 red[8]; __shared__ float4 st;
    if (!(c & 31)) red[c >> 5] = v;
    __syncthreads();
    if (c == 0) {
        float4 a = red[0];
        #pragma unroll
        for (int i = 1; i < 8; i++) { a.x += red[i].x; a.y += red[i].y; a.z += red[i].z; a.w += red[i].w; }
        float mr = a.x * (1.f/256.f), ma = a.z * (1.f/256.f);
        st = make_float4(mr, rsqrtf(a.y*(1.f/256.f) - mr*mr + 1e-5f),
                         ma, rsqrtf(a.w*(1.f/256.f) - ma*ma + 1e-5f));
    }
    __syncthreads();
    float4 s = st; int o = t * 256 + c;
    float gc = g[c], bc = b[c];
    g_rw[o] = __float2bfloat16((xr - s.x) * s.y * gc + bc);
    g_aw[o] = __float2bfloat16((xa - s.z) * s.w * gc + bc);
}
__global__ void ln2_kernel(const float* __restrict__ g, const float* __restrict__ b) {
    int t = blockIdx.x, c = threadIdx.x;
    float x = g_x[t * 256 + c];
    float4 v = warp_red4(make_float4(x, x * x, 0.f, 0.f));
    __shared__ float4 red[8]; __shared__ float2 st;
    if (!(c & 31)) red[c >> 5] = v;
    __syncthreads();
    if (c == 0) {
        float sx = 0.f, sxx = 0.f;
        #pragma unroll
        for (int i = 0; i < 8; i++) { sx += red[i].x; sxx += red[i].y; }
        float m = sx * (1.f/256.f);
        st = make_float2(m, rsqrtf(sxx*(1.f/256.f) - m*m + 1e-5f));
    }
    __syncthreads();
    float2 s = st;
    g_l2[t * 256 + c] = __float2bfloat16((x - s.x) * s.y * g[c] + b[c]);
}

// ---------------- bf16 mma.sync GEMM: BM=128, BN=128, BK=32, 5 stages ----------
#define ST 5
#define TILE_B 10240
#define STG_BYTES 20480
#define GEMM_SMEM (ST * STG_BYTES)   // 100 KB

__device__ __forceinline__ void gload(uint32_t sA,
        const __nv_bfloat16* Ab, const __nv_bfloat16* Bb, int K, int k0, int tid) {
    uint32_t sB = sA + TILE_B;
    #pragma unroll
    for (int i = 0; i < 2; i++) {
        int id = tid + (i << 8);
        int r = id >> 2, u = id & 3;
        uint32_t off = (uint32_t)r * 80 + (u << 4);
        cp16(sA + off, Ab + (size_t)r * K + k0 + (u << 3));
        cp16(sB + off, Bb + (size_t)r * K + k0 + (u << 3));
    }
}

// MODE 0: f32 out  1: proj scatter+residual  2: gelu->bf16  3: +extra f32  4: bf16 out
template <int MODE>
__global__ void __launch_bounds__(256, 2)
gemm_mma(const __nv_bfloat16* __restrict__ A, const __nv_bfloat16* __restrict__ Bt,
         const float* __restrict__ bias, float* __restrict__ C,
         int K, int N, const float* __restrict__ extra) {
    extern __shared__ __align__(128) char smem[];
    uint32_t sbase = smem_u32(smem);
    int tid = threadIdx.x;
    int lane = tid & 31, wid = tid >> 5;
    int wm = wid & 3, wn = wid >> 2;
    size_t bm = (size_t)blockIdx.y << 7;
    int bn = blockIdx.x << 7;

    const __nv_bfloat16* Ab = A + bm * K;
    const __nv_bfloat16* Bb = Bt + (size_t)bn * K;
    int nch = K >> 5;

    float c[2][8][4];
    #pragma unroll
    for (int i = 0; i < 2; i++)
        #pragma unroll
        for (int j = 0; j < 8; j++)
            #pragma unroll
            for (int k = 0; k < 4; k++) c[i][j][k] = 0.f;

    for (int p = 0; p < ST - 1; p++) {
        gload(sbase + p * STG_BYTES, Ab, Bb, K, p << 5, tid);
        cp_commit();
    }

    int sc = 0, sl = ST - 1;   // compute stage, load stage (avoid % in loop)
    for (int it = 0; it < nch; it++) {
        cp_wait3();
        __syncthreads();
        if (it + ST - 1 < nch)
            gload(sbase + sl * STG_BYTES, Ab, Bb, K, (it + ST - 1) << 5, tid);
        cp_commit();

        uint32_t sA = sbase + sc * STG_BYTES;
        uint32_t sB = sA + TILE_B;
        #pragma unroll
        for (int kc = 0; kc < 2; kc++) {
            uint32_t a[2][4], b[4][4];
            #pragma unroll
            for (int mf = 0; mf < 2; mf++) {
                int row = (wm << 5) + (mf << 4) + (lane & 7) + (((lane >> 3) & 1) << 3);
                int u = (kc << 1) + (lane >> 4);
                LDSM4(a[mf][0], a[mf][1], a[mf][2], a[mf][3],
                      sA + (uint32_t)row * 80 + (u << 4));
            }
            #pragma unroll
            for (int g = 0; g < 4; g++) {
                int row = (wn << 6) + (g << 4) + (lane & 7) + ((lane >> 4) << 3);
                int u = (kc << 1) + ((lane >> 3) & 1);
                LDSM4(b[g][0], b[g][1], b[g][2], b[g][3],
                      sB + (uint32_t)row * 80 + (u << 4));
            }
            #pragma unroll
            for (int mf = 0; mf < 2; mf++) {
                #pragma unroll
                for (int g = 0; g < 4; g++) {
                    MMAB(c[mf][2 * g],     a[mf], b[g][0], b[g][1]);
                    MMAB(c[mf][2 * g + 1], a[mf], b[g][2], b[g][3]);
                }
            }
        }
        sc++; if (sc == ST) sc = 0;
        sl++; if (sl == ST) sl = 0;
    }

    // ---- epilogue ----
    int lr4 = lane >> 2, lc = (lane & 3) << 1;
    #pragma unroll
    for (int mf = 0; mf < 2; mf++) {
        int r0 = (int)bm + (wm << 5) + (mf << 4) + lr4;
        #pragma unroll
        for (int h = 0; h < 2; h++) {
            int row = r0 + (h << 3);
            size_t drow;
            if (MODE == 1) drow = (size_t)shifted_row(row);
            else drow = (size_t)row;
            #pragma unroll
            for (int nf = 0; nf < 8; nf++) {
                int col = bn + (wn << 6) + (nf << 3) + lc;
                float vx = c[mf][nf][2 * h]     + bias[col];
                float vy = c[mf][nf][2 * h + 1] + bias[col + 1];
                if (MODE == 2) {
                    vx = 0.5f * vx * (1.f + erff(vx * 0.70710678118654752f));
                    vy = 0.5f * vy * (1.f + erff(vy * 0.70710678118654752f));
                    __nv_bfloat16* Cb = (__nv_bfloat16*)C;
                    *(__nv_bfloat162*)&Cb[drow * (size_t)N + col] =
                        __floats2bfloat162_rn(vx, vy);
                } else if (MODE == 4) {
                    __nv_bfloat16* Cb = (__nv_bfloat16*)C;
                    *(__nv_bfloat162*)&Cb[drow * (size_t)N + col] =
                        __floats2bfloat162_rn(vx, vy);
                } else if (MODE == 1) {
                    float2 e = *(const float2*)&extra[drow * 256 + col];
                    vx += e.x; vy += e.y;
                    *(float2*)&C[drow * 256 + col] = make_float2(vx, vy);
                } else if (MODE == 3) {
                    float2 e = *(const float2*)&extra[drow * 256 + col];
                    vx += e.x; vy += e.y;
                    *(float2*)&C[drow * (size_t)N + col] = make_float2(vx, vy);
                } else {
                    *(float2*)&C[drow * (size_t)N + col] = make_float2(vx, vy);
                }
            }
        }
    }
}

// ---------------- windowed attention -------------------------------------------
// 128 thr/block = one (window, head); thread (n, half) owns 16 head-dims.
// q/kv read as bf16; combined bias+mask table: one coalesced LDG per key.
__global__ void __launch_bounds__(128)
attn_kernel(const __nv_bfloat16* __restrict__ q, const __nv_bfloat16* __restrict__ kv,
            const float* __restrict__ cmb, __nv_bfloat16* __restrict__ out) {
    __shared__ float ks[64][36];
    __shared__ float vs[64][36];
    int blk = blockIdx.x;
    int b_ = blk >> 3, head = blk & 7;
    int tid = threadIdx.x;
    int n = tid >> 1, half = tid & 1;
    int t0 = b_ << 6;
    int hoff = half << 4;
    int dbase = (head << 5) + hoff;

    const __nv_bfloat16* kvrow = kv + (size_t)(t0 + n) * 512 + dbase;
    #pragma unroll
    for (int j = 0; j < 2; j++) {
        uint4 uk = *(const uint4*)(kvrow + 8 * j);
        uint4 uv = *(const uint4*)(kvrow + 256 + 8 * j);
        const __nv_bfloat162* pk = (const __nv_bfloat162*)&uk;
        const __nv_bfloat162* pv = (const __nv_bfloat162*)&uv;
        #pragma unroll
        for (int i = 0; i < 4; i++) {
            float2 fk = __bfloat1622float2(pk[i]);
            float2 fv = __bfloat1622float2(pv[i]);
            ks[n][hoff + 8*j + 2*i]     = fk.x;
            ks[n][hoff + 8*j + 2*i + 1] = fk.y;
            vs[n][hoff + 8*j + 2*i]     = fv.x;
            vs[n][hoff + 8*j + 2*i + 1] = fv.y;
        }
    }
    float qr[16];
    const __nv_bfloat16* qrow = q + (size_t)(t0 + n) * 256 + dbase;
    #pragma unroll
    for (int j = 0; j < 2; j++) {
        uint4 uq = *(const uint4*)(qrow + 8 * j);
        const __nv_bfloat162* pq = (const __nv_bfloat162*)&uq;
        #pragma unroll
        for (int i = 0; i < 4; i++) {
            float2 f = __bfloat1622float2(pq[i]);
            qr[8*j + 2*i] = f.x; qr[8*j + 2*i + 1] = f.y;
        }
    }
    __syncthreads();

    // combined bias+mask row: [combo][m][n] layout -> stride 64 in m
    const float* crow = cmb + ((size_t)(((b_ & 255) << 3) + head) << 12) + n;
    const float scale = 0.17677669529663687f;

    float accv[16];
    #pragma unroll
    for (int d = 0; d < 16; d++) accv[d] = 0.f;
    float sum = 0.f;
    #pragma unroll 4
    for (int m = 0; m < 64; m++) {
        float dp = 0.f;
        #pragma unroll
        for (int j4 = 0; j4 < 4; j4++) {
            float4 kf = *(const float4*)&ks[m][hoff + 4 * j4];
            dp += qr[4*j4+0]*kf.x + qr[4*j4+1]*kf.y + qr[4*j4+2]*kf.z + qr[4*j4+3]*kf.w;
        }
        float dot = dp + __shfl_xor_sync(~0u, dp, 1);
        float e = __expf(dot * scale + crow[m << 6]);
        sum += e;
        #pragma unroll
        for (int j4 = 0; j4 < 4; j4++) {
            float4 vf = *(const float4*)&vs[m][hoff + 4 * j4];
            accv[4*j4+0] += e * vf.x; accv[4*j4+1] += e * vf.y;
            accv[4*j4+2] += e * vf.z; accv[4*j4+3] += e * vf.w;
        }
    }
    float inv = 1.f / sum;
    __nv_bfloat16* orow = out + (size_t)(t0 + n) * 256 + dbase;
    #pragma unroll
    for (int i = 0; i < 8; i++)
        *(__nv_bfloat162*)&orow[2 * i] =
            __floats2bfloat162_rn(accv[2*i] * inv, accv[2*i+1] * inv);
}

// ---------------- launch -------------------------------------------------------
extern "C" void kernel_launch(void* const* d_in, const int* in_sizes, int n_in,
                              void* d_out, int out_size) {
    (void)in_sizes; (void)n_in; (void)out_size;
    const float* ref  = (const float*)d_in[0];
    const float* adj  = (const float*)d_in[1];
    const float* mask = (const float*)d_in[2];
    const float* n1g = (const float*)d_in[5];
    const float* n1b = (const float*)d_in[6];
    const float* qw  = (const float*)d_in[7];
    const float* qb  = (const float*)d_in[8];
    const float* kvw = (const float*)d_in[9];
    const float* kvb = (const float*)d_in[10];
    const float* rel = (const float*)d_in[11];
    const float* pw  = (const float*)d_in[12];
    const float* pb  = (const float*)d_in[13];
    const float* n2g = (const float*)d_in[14];
    const float* n2b = (const float*)d_in[15];
    const float* f1w = (const float*)d_in[16];
    const float* f1b = (const float*)d_in[17];
    const float* f2w = (const float*)d_in[18];
    const float* f2b = (const float*)d_in[19];
    float* out = (float*)d_out;

    float *x, *cmb;
    __nv_bfloat16 *q, *kv, *rw, *aw, *ao, *l2, *h, *wt;
    cudaGetSymbolAddress((void**)&x,   g_x);
    cudaGetSymbolAddress((void**)&cmb, g_cmb);
    cudaGetSymbolAddress((void**)&q,   g_q);
    cudaGetSymbolAddress((void**)&kv,  g_kv);
    cudaGetSymbolAddress((void**)&rw,  g_rw);
    cudaGetSymbolAddress((void**)&aw,  g_aw);
    cudaGetSymbolAddress((void**)&ao,  g_ao);
    cudaGetSymbolAddress((void**)&l2,  g_l2);
    cudaGetSymbolAddress((void**)&h,   g_h);
    cudaGetSymbolAddress((void**)&wt,  g_wt);

    cudaFuncSetAttribute(gemm_mma<1>, cudaFuncAttributeMaxDynamicSharedMemorySize, GEMM_SMEM);
    cudaFuncSetAttribute(gemm_mma<2>, cudaFuncAttributeMaxDynamicSharedMemorySize, GEMM_SMEM);
    cudaFuncSetAttribute(gemm_mma<3>, cudaFuncAttributeMaxDynamicSharedMemorySize, GEMM_SMEM);
    cudaFuncSetAttribute(gemm_mma<4>, cudaFuncAttributeMaxDynamicSharedMemorySize, GEMM_SMEM);

    transpose_all<<<768, dim3(32, 8)>>>(qw, kvw, pw, f1w, f2w, wt);
    build_cmb<<<2048, 256>>>(rel, mask, cmb);
    ln1_kernel<<<TOK, 256>>>(ref, adj, n1g, n1b);
    gemm_mma<4><<<dim3(2, 1024), 256, GEMM_SMEM>>>(rw, wt + WT_Q,  qb,  (float*)q,  256, 256,  nullptr);
    gemm_mma<4><<<dim3(4, 1024), 256, GEMM_SMEM>>>(aw, wt + WT_KV, kvb, (float*)kv, 256, 512,  nullptr);
    attn_kernel<<<16384, 128>>>(q, kv, cmb, ao);
    gemm_mma<1><<<dim3(2, 1024), 256, GEMM_SMEM>>>(ao, wt + WT_P,  pb,  x,  256, 256,  ref);
    ln2_kernel<<<TOK, 256>>>(n2g, n2b);
    gemm_mma<2><<<dim3(8, 1024), 256, GEMM_SMEM>>>(l2, wt + WT_F1, f1b, (float*)h, 256, 1024, nullptr);
    gemm_mma<3><<<dim3(2, 1024), 256, GEMM_SMEM>>>(h,  wt + WT_F2, f2b, out, 1024, 256, x);
}

// round 12
// speedup vs baseline: 6.4542x; 1.1692x over previous
#include <cuda_runtime.h>
#include <cuda_bf16.h>
#include <math.h>
#include <stdint.h>

#define TOK 131072
#define CCH 256
#define HID 1024

// fp32 (numerically sensitive)
static __device__ float g_x [(size_t)TOK * CCH];
static __device__ float g_cmb[2048 * 4096];          // bias+mask, [combo][m][n]
// bf16 (mma / attention operands)
static __device__ __nv_bfloat16 g_q [(size_t)TOK * CCH];
static __device__ __nv_bfloat16 g_kv[(size_t)TOK * 2 * CCH];
static __device__ __nv_bfloat16 g_rw[(size_t)TOK * CCH];
static __device__ __nv_bfloat16 g_aw[(size_t)TOK * CCH];
static __device__ __nv_bfloat16 g_ao[(size_t)TOK * CCH];
static __device__ __nv_bfloat16 g_l2[(size_t)TOK * CCH];
static __device__ __nv_bfloat16 g_h [(size_t)TOK * HID];
static __device__ __nv_bfloat16 g_wt[786432];
#define WT_Q   0
#define WT_KV  65536
#define WT_P   196608
#define WT_F1  262144
#define WT_F2  524288

// ---------------- helpers ------------------------------------------------------
__device__ __forceinline__ uint32_t smem_u32(const void* p) {
    uint32_t a;
    asm("{ .reg .u64 t; cvta.to.shared.u64 t, %1; cvt.u32.u64 %0, t; }" : "=r"(a) : "l"(p));
    return a;
}
__device__ __forceinline__ void cp16(uint32_t dst, const void* src) {
    asm volatile("cp.async.cg.shared.global [%0], [%1], 16;" :: "r"(dst), "l"(src));
}
__device__ __forceinline__ void cp_commit() { asm volatile("cp.async.commit_group;" ::: "memory"); }
__device__ __forceinline__ void cp_wait3()  { asm volatile("cp.async.wait_group 3;" ::: "memory"); }
__device__ __forceinline__ void cp_wait0()  { asm volatile("cp.async.wait_group 0;" ::: "memory"); }

#define LDSM4(r0, r1, r2, r3, addr) \
    asm volatile("ldmatrix.sync.aligned.m8n8.x4.shared.b16 {%0,%1,%2,%3}, [%4];" \
        : "=r"(r0), "=r"(r1), "=r"(r2), "=r"(r3) : "r"(addr))

#define MMAB(c, a, b0, b1) \
    asm volatile("mma.sync.aligned.m16n8k16.row.col.f32.bf16.bf16.f32 " \
        "{%0,%1,%2,%3}, {%4,%5,%6,%7}, {%8,%9}, {%0,%1,%2,%3};" \
        : "+f"((c)[0]), "+f"((c)[1]), "+f"((c)[2]), "+f"((c)[3]) \
        : "r"((a)[0]), "r"((a)[1]), "r"((a)[2]), "r"((a)[3]), "r"(b0), "r"(b1))

__device__ __forceinline__ int shifted_row(int t) {
    int b_ = t >> 6, n = t & 63;
    int bi = b_ >> 8, wi = b_ & 255;
    int h = ((((wi >> 4) << 3) | (n >> 3)) + 4) & 127;
    int w = ((((wi & 15) << 3) | (n & 7)) + 4) & 127;
    return (bi << 14) | (h << 7) | w;
}

// ---------------- fused weight transpose ---------------------------------------
__global__ void transpose_all(const float* __restrict__ qw, const float* __restrict__ kvw,
                              const float* __restrict__ pw, const float* __restrict__ f1w,
                              const float* __restrict__ f2w, __nv_bfloat16* __restrict__ wt) {
    __shared__ float t[32][33];
    int b = blockIdx.x;
    const float* W; __nv_bfloat16* Wt; int K, N, nx, local;
    if (b < 64)       { W = qw;  Wt = wt + WT_Q;  K = 256;  N = 256;  nx = 8;  local = b; }
    else if (b < 192) { W = kvw; Wt = wt + WT_KV; K = 256;  N = 512;  nx = 16; local = b - 64; }
    else if (b < 256) { W = pw;  Wt = wt + WT_P;  K = 256;  N = 256;  nx = 8;  local = b - 192; }
    else if (b < 512) { W = f1w; Wt = wt + WT_F1; K = 256;  N = 1024; nx = 32; local = b - 256; }
    else              { W = f2w; Wt = wt + WT_F2; K = 1024; N = 256;  nx = 8;  local = b - 512; }
    int n0 = (local % nx) << 5, k0 = (local / nx) << 5;
    int tx = threadIdx.x, ty = threadIdx.y;
    #pragma unroll
    for (int j = 0; j < 32; j += 8) t[ty + j][tx] = W[(size_t)(k0 + ty + j) * N + n0 + tx];
    __syncthreads();
    #pragma unroll
    for (int j = 0; j < 32; j += 8)
        Wt[(size_t)(n0 + ty + j) * K + k0 + tx] = __float2bfloat16(t[tx][ty + j]);
}

// ---------------- bias+mask precombine: cmb[combo][m][n] -----------------------
__global__ void build_cmb(const float* __restrict__ rel, const float* __restrict__ mask,
                          float* __restrict__ cmb) {
    int combo = blockIdx.x;
    int win = combo >> 3, head = combo & 7;
    const float* mwin = mask + win * 4096;
    float* dst = cmb + (size_t)combo * 4096;
    for (int id = threadIdx.x; id < 4096; id += 256) {
        int m = id >> 6, n = id & 63;
        int idx = ((n >> 3) - (m >> 3) + 7) * 15 + ((n & 7) - (m & 7) + 7);
        dst[id] = rel[idx * 8 + head] + mwin[n * 64 + m];
    }
}

// ---------------- LayerNorms: warp per token -----------------------------------
__global__ void __launch_bounds__(256)
ln1_kernel(const float* __restrict__ ref, const float* __restrict__ adj,
           const float* __restrict__ g, const float* __restrict__ b) {
    int t = (blockIdx.x << 3) + (threadIdx.x >> 5);
    int lane = threadIdx.x & 31;
    int base = shifted_row(t) * 256 + (lane << 3);
    float4 r0 = *(const float4*)(ref + base);
    float4 r1 = *(const float4*)(ref + base + 4);
    float4 a0 = *(const float4*)(adj + base);
    float4 a1 = *(const float4*)(adj + base + 4);
    float xr[8] = {r0.x, r0.y, r0.z, r0.w, r1.x, r1.y, r1.z, r1.w};
    float xa[8] = {a0.x, a0.y, a0.z, a0.w, a1.x, a1.y, a1.z, a1.w};
    float sr = 0.f, sr2 = 0.f, sa = 0.f, sa2 = 0.f;
    #pragma unroll
    for (int i = 0; i < 8; i++) {
        sr += xr[i]; sr2 += xr[i] * xr[i];
        sa += xa[i]; sa2 += xa[i] * xa[i];
    }
    #pragma unroll
    for (int o = 16; o > 0; o >>= 1) {
        sr  += __shfl_xor_sync(~0u, sr,  o); sr2 += __shfl_xor_sync(~0u, sr2, o);
        sa  += __shfl_xor_sync(~0u, sa,  o); sa2 += __shfl_xor_sync(~0u, sa2, o);
    }
    float mr = sr * (1.f/256.f), ma = sa * (1.f/256.f);
    float rr = rsqrtf(sr2 * (1.f/256.f) - mr * mr + 1e-5f);
    float ra = rsqrtf(sa2 * (1.f/256.f) - ma * ma + 1e-5f);
    int c0 = lane << 3;
    float4 g0 = *(const float4*)(g + c0), g1 = *(const float4*)(g + c0 + 4);
    float4 b0 = *(const float4*)(b + c0), b1 = *(const float4*)(b + c0 + 4);
    float gg[8] = {g0.x, g0.y, g0.z, g0.w, g1.x, g1.y, g1.z, g1.w};
    float bb[8] = {b0.x, b0.y, b0.z, b0.w, b1.x, b1.y, b1.z, b1.w};
    __nv_bfloat162 pr[4], pa[4];
    #pragma unroll
    for (int i = 0; i < 4; i++) {
        pr[i] = __floats2bfloat162_rn((xr[2*i] - mr) * rr * gg[2*i] + bb[2*i],
                                      (xr[2*i+1] - mr) * rr * gg[2*i+1] + bb[2*i+1]);
        pa[i] = __floats2bfloat162_rn((xa[2*i] - ma) * ra * gg[2*i] + bb[2*i],
                                      (xa[2*i+1] - ma) * ra * gg[2*i+1] + bb[2*i+1]);
    }
    int o = t * 256 + c0;
    *(uint4*)&g_rw[o] = *(uint4*)pr;
    *(uint4*)&g_aw[o] = *(uint4*)pa;
}
__global__ void __launch_bounds__(256)
ln2_kernel(const float* __restrict__ g, const float* __restrict__ b) {
    int t = (blockIdx.x << 3) + (threadIdx.x >> 5);
    int lane = threadIdx.x & 31;
    int base = t * 256 + (lane << 3);
    float4 x0 = *(const float4*)(g_x + base);
    float4 x1 = *(const float4*)(g_x + base + 4);
    float xv[8] = {x0.x, x0.y, x0.z, x0.w, x1.x, x1.y, x1.z, x1.w};
    float s = 0.f, s2 = 0.f;
    #pragma unroll
    for (int i = 0; i < 8; i++) { s += xv[i]; s2 += xv[i] * xv[i]; }
    #pragma unroll
    for (int o = 16; o > 0; o >>= 1) {
        s += __shfl_xor_sync(~0u, s, o); s2 += __shfl_xor_sync(~0u, s2, o);
    }
    float m = s * (1.f/256.f);
    float r = rsqrtf(s2 * (1.f/256.f) - m * m + 1e-5f);
    int c0 = lane << 3;
    float4 g0 = *(const float4*)(g + c0), g1 = *(const float4*)(g + c0 + 4);
    float4 b0 = *(const float4*)(b + c0), b1 = *(const float4*)(b + c0 + 4);
    float gg[8] = {g0.x, g0.y, g0.z, g0.w, g1.x, g1.y, g1.z, g1.w};
    float bb[8] = {b0.x, b0.y, b0.z, b0.w, b1.x, b1.y, b1.z, b1.w};
    __nv_bfloat162 p[4];
    #pragma unroll
    for (int i = 0; i < 4; i++)
        p[i] = __floats2bfloat162_rn((xv[2*i] - m) * r * gg[2*i] + bb[2*i],
                                     (xv[2*i+1] - m) * r * gg[2*i+1] + bb[2*i+1]);
    *(uint4*)&g_l2[base] = *(uint4*)p;
}

// ---------------- bf16 mma.sync GEMM: BM=128, BN=128, BK=32, 5 stages ----------
#define ST 5
#define TILE_B 10240
#define STG_BYTES 20480
#define GEMM_SMEM (ST * STG_BYTES)   // 100 KB

__device__ __forceinline__ void gload(uint32_t sA,
        const __nv_bfloat16* Ab, const __nv_bfloat16* Bb, int K, int k0, int tid) {
    uint32_t sB = sA + TILE_B;
    #pragma unroll
    for (int i = 0; i < 2; i++) {
        int id = tid + (i << 8);
        int r = id >> 2, u = id & 3;
        uint32_t off = (uint32_t)r * 80 + (u << 4);
        cp16(sA + off, Ab + (size_t)r * K + k0 + (u << 3));
        cp16(sB + off, Bb + (size_t)r * K + k0 + (u << 3));
    }
}

// MODE 0: f32 out  1: proj scatter+residual  2: gelu->bf16  3: +extra f32
// MODE 4: bf16 out 5: bf16 out * attn scale (q)
template <int MODE>
__global__ void __launch_bounds__(256, 2)
gemm_mma(const __nv_bfloat16* __restrict__ A, const __nv_bfloat16* __restrict__ Bt,
         const float* __restrict__ bias, float* __restrict__ C,
         int K, int N, const float* __restrict__ extra) {
    extern __shared__ __align__(128) char smem[];
    uint32_t sbase = smem_u32(smem);
    int tid = threadIdx.x;
    int lane = tid & 31, wid = tid >> 5;
    int wm = wid & 3, wn = wid >> 2;
    size_t bm = (size_t)blockIdx.y << 7;
    int bn = blockIdx.x << 7;

    const __nv_bfloat16* Ab = A + bm * K;
    const __nv_bfloat16* Bb = Bt + (size_t)bn * K;
    int nch = K >> 5;

    float c[2][8][4];
    #pragma unroll
    for (int i = 0; i < 2; i++)
        #pragma unroll
        for (int j = 0; j < 8; j++)
            #pragma unroll
            for (int k = 0; k < 4; k++) c[i][j][k] = 0.f;

    for (int p = 0; p < ST - 1; p++) {
        gload(sbase + p * STG_BYTES, Ab, Bb, K, p << 5, tid);
        cp_commit();
    }

    int sc = 0, sl = ST - 1;
    for (int it = 0; it < nch; it++) {
        cp_wait3();
        __syncthreads();
        if (it + ST - 1 < nch)
            gload(sbase + sl * STG_BYTES, Ab, Bb, K, (it + ST - 1) << 5, tid);
        cp_commit();

        uint32_t sA = sbase + sc * STG_BYTES;
        uint32_t sB = sA + TILE_B;
        #pragma unroll
        for (int kc = 0; kc < 2; kc++) {
            uint32_t a[2][4], b[4][4];
            #pragma unroll
            for (int mf = 0; mf < 2; mf++) {
                int row = (wm << 5) + (mf << 4) + (lane & 7) + (((lane >> 3) & 1) << 3);
                int u = (kc << 1) + (lane >> 4);
                LDSM4(a[mf][0], a[mf][1], a[mf][2], a[mf][3],
                      sA + (uint32_t)row * 80 + (u << 4));
            }
            #pragma unroll
            for (int g = 0; g < 4; g++) {
                int row = (wn << 6) + (g << 4) + (lane & 7) + ((lane >> 4) << 3);
                int u = (kc << 1) + ((lane >> 3) & 1);
                LDSM4(b[g][0], b[g][1], b[g][2], b[g][3],
                      sB + (uint32_t)row * 80 + (u << 4));
            }
            #pragma unroll
            for (int mf = 0; mf < 2; mf++) {
                #pragma unroll
                for (int g = 0; g < 4; g++) {
                    MMAB(c[mf][2 * g],     a[mf], b[g][0], b[g][1]);
                    MMAB(c[mf][2 * g + 1], a[mf], b[g][2], b[g][3]);
                }
            }
        }
        sc++; if (sc == ST) sc = 0;
        sl++; if (sl == ST) sl = 0;
    }

    // ---- epilogue ----
    int lr4 = lane >> 2, lc = (lane & 3) << 1;
    #pragma unroll
    for (int mf = 0; mf < 2; mf++) {
        int r0 = (int)bm + (wm << 5) + (mf << 4) + lr4;
        #pragma unroll
        for (int h = 0; h < 2; h++) {
            int row = r0 + (h << 3);
            size_t drow;
            if (MODE == 1) drow = (size_t)shifted_row(row);
            else drow = (size_t)row;
            #pragma unroll
            for (int nf = 0; nf < 8; nf++) {
                int col = bn + (wn << 6) + (nf << 3) + lc;
                float vx = c[mf][nf][2 * h]     + bias[col];
                float vy = c[mf][nf][2 * h + 1] + bias[col + 1];
                if (MODE == 2) {
                    vx = 0.5f * vx * (1.f + erff(vx * 0.70710678118654752f));
                    vy = 0.5f * vy * (1.f + erff(vy * 0.70710678118654752f));
                    __nv_bfloat16* Cb = (__nv_bfloat16*)C;
                    *(__nv_bfloat162*)&Cb[drow * (size_t)N + col] =
                        __floats2bfloat162_rn(vx, vy);
                } else if (MODE == 4 || MODE == 5) {
                    if (MODE == 5) {
                        vx *= 0.17677669529663687f;
                        vy *= 0.17677669529663687f;
                    }
                    __nv_bfloat16* Cb = (__nv_bfloat16*)C;
                    *(__nv_bfloat162*)&Cb[drow * (size_t)N + col] =
                        __floats2bfloat162_rn(vx, vy);
                } else if (MODE == 1) {
                    float2 e = *(const float2*)&extra[drow * 256 + col];
                    vx += e.x; vy += e.y;
                    *(float2*)&C[drow * 256 + col] = make_float2(vx, vy);
                } else if (MODE == 3) {
                    float2 e = *(const float2*)&extra[drow * 256 + col];
                    vx += e.x; vy += e.y;
                    *(float2*)&C[drow * (size_t)N + col] = make_float2(vx, vy);
                } else {
                    *(float2*)&C[drow * (size_t)N + col] = make_float2(vx, vy);
                }
            }
        }
    }
}

// ---------------- windowed attention -------------------------------------------
// 128 thr = one (window, head); thread (n, half) owns 16 head-dims.
// cmb slice staged in smem via cp.async; 16-wide phased key loop.
__global__ void __launch_bounds__(128)
attn_kernel(const __nv_bfloat16* __restrict__ q, const __nv_bfloat16* __restrict__ kv,
            const float* __restrict__ cmb, __nv_bfloat16* __restrict__ out) {
    __shared__ float ks[64][36];
    __shared__ float vs[64][36];
    __shared__ float cmbs[4096];
    int blk = blockIdx.x;
    int b_ = blk >> 3, head = blk & 7;
    int tid = threadIdx.x;
    int n = tid >> 1, half = tid & 1;
    int t0 = b_ << 6;
    int hoff = half << 4;
    int dbase = (head << 5) + hoff;

    // stage cmb slice (16 KB) with cp.async
    {
        uint32_t cb = smem_u32(cmbs);
        const float* csrc = cmb + ((size_t)(((b_ & 255) << 3) + head) << 12);
        #pragma unroll
        for (int i = 0; i < 8; i++) {
            int id = tid + (i << 7);
            cp16(cb + id * 16, csrc + id * 4);
        }
        cp_commit();
    }

    const __nv_bfloat16* kvrow = kv + (size_t)(t0 + n) * 512 + dbase;
    #pragma unroll
    for (int j = 0; j < 2; j++) {
        uint4 uk = *(const uint4*)(kvrow + 8 * j);
        uint4 uv = *(const uint4*)(kvrow + 256 + 8 * j);
        const __nv_bfloat162* pk = (const __nv_bfloat162*)&uk;
        const __nv_bfloat162* pv = (const __nv_bfloat162*)&uv;
        #pragma unroll
        for (int i = 0; i < 4; i++) {
            float2 fk = __bfloat1622float2(pk[i]);
            float2 fv = __bfloat1622float2(pv[i]);
            ks[n][hoff + 8*j + 2*i]     = fk.x;
            ks[n][hoff + 8*j + 2*i + 1] = fk.y;
            vs[n][hoff + 8*j + 2*i]     = fv.x;
            vs[n][hoff + 8*j + 2*i + 1] = fv.y;
        }
    }
    float qr[16];
    const __nv_bfloat16* qrow = q + (size_t)(t0 + n) * 256 + dbase;
    #pragma unroll
    for (int j = 0; j < 2; j++) {
        uint4 uq = *(const uint4*)(qrow + 8 * j);
        const __nv_bfloat162* pq = (const __nv_bfloat162*)&uq;
        #pragma unroll
        for (int i = 0; i < 4; i++) {
            float2 f = __bfloat1622float2(pq[i]);
            qr[8*j + 2*i] = f.x; qr[8*j + 2*i + 1] = f.y;
        }
    }
    cp_wait0();
    __syncthreads();

    float accv[16];
    #pragma unroll
    for (int d = 0; d < 16; d++) accv[d] = 0.f;
    float sum = 0.f;
    #pragma unroll 1
    for (int mt = 0; mt < 64; mt += 16) {
        float e[16];
        #pragma unroll
        for (int i = 0; i < 16; i++) {
            int m = mt + i;
            float dp = 0.f;
            #pragma unroll
            for (int j4 = 0; j4 < 4; j4++) {
                float4 kf = *(const float4*)&ks[m][hoff + 4 * j4];
                dp += qr[4*j4+0]*kf.x + qr[4*j4+1]*kf.y + qr[4*j4+2]*kf.z + qr[4*j4+3]*kf.w;
            }
            float dot = dp + __shfl_xor_sync(~0u, dp, 1);
            e[i] = __expf(dot + cmbs[(m << 6) + n]);   // scale pre-folded into q
        }
        #pragma unroll
        for (int i = 0; i < 16; i++) {
            int m = mt + i;
            sum += e[i];
            #pragma unroll
            for (int j4 = 0; j4 < 4; j4++) {
                float4 vf = *(const float4*)&vs[m][hoff + 4 * j4];
                accv[4*j4+0] += e[i] * vf.x; accv[4*j4+1] += e[i] * vf.y;
                accv[4*j4+2] += e[i] * vf.z; accv[4*j4+3] += e[i] * vf.w;
            }
        }
    }
    float inv = 1.f / sum;
    __nv_bfloat16* orow = out + (size_t)(t0 + n) * 256 + dbase;
    #pragma unroll
    for (int i = 0; i < 8; i++)
        *(__nv_bfloat162*)&orow[2 * i] =
            __floats2bfloat162_rn(accv[2*i] * inv, accv[2*i+1] * inv);
}

// ---------------- launch -------------------------------------------------------
extern "C" void kernel_launch(void* const* d_in, const int* in_sizes, int n_in,
                              void* d_out, int out_size) {
    (void)in_sizes; (void)n_in; (void)out_size;
    const float* ref  = (const float*)d_in[0];
    const float* adj  = (const float*)d_in[1];
    const float* mask = (const float*)d_in[2];
    const float* n1g = (const float*)d_in[5];
    const float* n1b = (const float*)d_in[6];
    const float* qw  = (const float*)d_in[7];
    const float* qb  = (const float*)d_in[8];
    const float* kvw = (const float*)d_in[9];
    const float* kvb = (const float*)d_in[10];
    const float* rel = (const float*)d_in[11];
    const float* pw  = (const float*)d_in[12];
    const float* pb  = (const float*)d_in[13];
    const float* n2g = (const float*)d_in[14];
    const float* n2b = (const float*)d_in[15];
    const float* f1w = (const float*)d_in[16];
    const float* f1b = (const float*)d_in[17];
    const float* f2w = (const float*)d_in[18];
    const float* f2b = (const float*)d_in[19];
    float* out = (float*)d_out;

    float *x, *cmb;
    __nv_bfloat16 *q, *kv, *rw, *aw, *ao, *l2, *h, *wt;
    cudaGetSymbolAddress((void**)&x,   g_x);
    cudaGetSymbolAddress((void**)&cmb, g_cmb);
    cudaGetSymbolAddress((void**)&q,   g_q);
    cudaGetSymbolAddress((void**)&kv,  g_kv);
    cudaGetSymbolAddress((void**)&rw,  g_rw);
    cudaGetSymbolAddress((void**)&aw,  g_aw);
    cudaGetSymbolAddress((void**)&ao,  g_ao);
    cudaGetSymbolAddress((void**)&l2,  g_l2);
    cudaGetSymbolAddress((void**)&h,   g_h);
    cudaGetSymbolAddress((void**)&wt,  g_wt);

    cudaFuncSetAttribute(gemm_mma<1>, cudaFuncAttributeMaxDynamicSharedMemorySize, GEMM_SMEM);
    cudaFuncSetAttribute(gemm_mma<2>, cudaFuncAttributeMaxDynamicSharedMemorySize, GEMM_SMEM);
    cudaFuncSetAttribute(gemm_mma<3>, cudaFuncAttributeMaxDynamicSharedMemorySize, GEMM_SMEM);
    cudaFuncSetAttribute(gemm_mma<4>, cudaFuncAttributeMaxDynamicSharedMemorySize, GEMM_SMEM);
    cudaFuncSetAttribute(gemm_mma<5>, cudaFuncAttributeMaxDynamicSharedMemorySize, GEMM_SMEM);

    transpose_all<<<768, dim3(32, 8)>>>(qw, kvw, pw, f1w, f2w, wt);
    build_cmb<<<2048, 256>>>(rel, mask, cmb);
    ln1_kernel<<<TOK / 8, 256>>>(ref, adj, n1g, n1b);
    gemm_mma<5><<<dim3(2, 1024), 256, GEMM_SMEM>>>(rw, wt + WT_Q,  qb,  (float*)q,  256, 256,  nullptr);
    gemm_mma<4><<<dim3(4, 1024), 256, GEMM_SMEM>>>(aw, wt + WT_KV, kvb, (float*)kv, 256, 512,  nullptr);
    attn_kernel<<<16384, 128>>>(q, kv, cmb, ao);
    gemm_mma<1><<<dim3(2, 1024), 256, GEMM_SMEM>>>(ao, wt + WT_P,  pb,  x,  256, 256,  ref);
    ln2_kernel<<<TOK / 8, 256>>>(n2g, n2b);
    gemm_mma<2><<<dim3(8, 1024), 256, GEMM_SMEM>>>(l2, wt + WT_F1, f1b, (float*)h, 256, 1024, nullptr);
    gemm_mma<3><<<dim3(2, 1024), 256, GEMM_SMEM>>>(h,  wt + WT_F2, f2b, out, 1024, 256, x);
}